// round 2
// baseline (speedup 1.0000x reference)
#include <cuda_runtime.h>
#include <math.h>

// Problem constants
#define BB   16
#define CC   512
#define NN   1024      // H*W = 32*32
#define NG   32        // num groups
#define CPG  16        // channels per group (512/32)
#define GSZ  (CPG*NN)  // elements per group = 16384

// Scratch (static device globals; no runtime allocation allowed)
__device__ float g_xn  [BB*CC*NN];   // normalized x
__device__ float g_q   [BB*CC*NN];
__device__ float g_k   [BB*CC*NN];
__device__ float g_v   [BB*CC*NN];
__device__ float g_attn[BB*NN*NN];   // attention logits / probs
__device__ float g_o   [BB*CC*NN];   // attention output

// ---------------------------------------------------------------------------
// GroupNorm: one block per (batch, group). Channels of a group are contiguous
// in [B, C, N] layout, so group bg starts at bg*CPG*NN.
// ---------------------------------------------------------------------------
__global__ __launch_bounds__(256) void gn_kernel(
    const float* __restrict__ x,
    const float* __restrict__ sc,
    const float* __restrict__ bi,
    float* __restrict__ out)
{
    const int bg = blockIdx.x;               // 0 .. BB*NG-1
    const float* xp = x   + (long)bg * GSZ;
    float*       op = out + (long)bg * GSZ;

    float s = 0.f, s2 = 0.f;
    for (int i = threadIdx.x; i < GSZ; i += 256) {
        float v = xp[i];
        s += v; s2 += v * v;
    }
    // warp reduce
    #pragma unroll
    for (int o = 16; o > 0; o >>= 1) {
        s  += __shfl_xor_sync(~0u, s,  o);
        s2 += __shfl_xor_sync(~0u, s2, o);
    }
    __shared__ float rs[8], rs2[8];
    const int wid = threadIdx.x >> 5, lid = threadIdx.x & 31;
    if (lid == 0) { rs[wid] = s; rs2[wid] = s2; }
    __syncthreads();
    if (threadIdx.x == 0) {
        float ts = 0.f, ts2 = 0.f;
        #pragma unroll
        for (int w = 0; w < 8; w++) { ts += rs[w]; ts2 += rs2[w]; }
        rs[0] = ts; rs2[0] = ts2;
    }
    __syncthreads();
    const float inv_n = 1.0f / (float)GSZ;
    const float mean  = rs[0] * inv_n;
    const float var   = rs2[0] * inv_n - mean * mean;
    const float rstd  = rsqrtf(var + 1e-5f);

    const int g = bg % NG;
    for (int i = threadIdx.x; i < GSZ; i += 256) {
        const int c = g * CPG + (i >> 10);   // i/NN
        op[i] = (xp[i] - mean) * rstd * sc[c] + bi[c];
    }
}

// ---------------------------------------------------------------------------
// Generic batched tiled SGEMM: C = alpha * op(A) * op(B)  (+ bias + resid)
//   128x128 block tile, K-step 8, 256 threads, 8x8 per-thread microtile.
//   TA: A element (m,k) read as A[k*lda + m]   (transposed storage)
//   TB: B element (k,n) read as B[n*ldb + k]
//   EPI: 0 = alpha only, 1 = + bias[m], 3 = + bias[m] + resid
// All dims divisible by tile sizes for this problem (512/1024), no bounds.
// ---------------------------------------------------------------------------
template<bool TA, bool TB, int EPI>
__global__ __launch_bounds__(256) void gemm_k(
    const float* __restrict__ Ag, long strideA,
    const float* __restrict__ Bg, long strideB,
    float*       __restrict__ Cg, long strideC,
    const float* __restrict__ bias,
    const float* __restrict__ resid, long strideR,
    int K, int lda, int ldb, int ldc, float alpha)
{
    __shared__ float As[8][128];
    __shared__ float Bs[8][128];

    const float* A = Ag + blockIdx.z * strideA;
    const float* B = Bg + blockIdx.z * strideB;
    float*       C = Cg + blockIdx.z * strideC;

    const int m0 = blockIdx.y * 128;
    const int n0 = blockIdx.x * 128;
    const int tid = threadIdx.x;
    const int tx = tid & 15, ty = tid >> 4;

    float acc[8][8];
    #pragma unroll
    for (int i = 0; i < 8; i++)
        #pragma unroll
        for (int j = 0; j < 8; j++) acc[i][j] = 0.f;

    for (int k0 = 0; k0 < K; k0 += 8) {
        #pragma unroll
        for (int i = 0; i < 4; i++) {
            const int idx = tid + i * 256;
            const int m  = idx >> 3;
            const int kk = idx & 7;
            As[kk][m] = TA ? A[(long)(k0 + kk) * lda + (m0 + m)]
                           : A[(long)(m0 + m) * lda + (k0 + kk)];
        }
        #pragma unroll
        for (int i = 0; i < 4; i++) {
            const int idx = tid + i * 256;
            const int kk = idx >> 7;
            const int n  = idx & 127;
            Bs[kk][n] = TB ? B[(long)(n0 + n) * ldb + (k0 + kk)]
                           : B[(long)(k0 + kk) * ldb + (n0 + n)];
        }
        __syncthreads();
        #pragma unroll
        for (int kk = 0; kk < 8; kk++) {
            float ra[8], rb[8];
            #pragma unroll
            for (int i = 0; i < 8; i++) ra[i] = As[kk][ty * 8 + i];
            #pragma unroll
            for (int j = 0; j < 8; j++) rb[j] = Bs[kk][tx * 8 + j];
            #pragma unroll
            for (int i = 0; i < 8; i++)
                #pragma unroll
                for (int j = 0; j < 8; j++)
                    acc[i][j] += ra[i] * rb[j];
        }
        __syncthreads();
    }

    #pragma unroll
    for (int i = 0; i < 8; i++) {
        const int m = m0 + ty * 8 + i;
        const float bv = (EPI >= 1) ? bias[m] : 0.f;
        #pragma unroll
        for (int j = 0; j < 8; j++) {
            const int n = n0 + tx * 8 + j;
            float v = acc[i][j] * alpha + bv;
            if (EPI == 3)
                v += resid[blockIdx.z * strideR + (long)m * ldc + n];
            C[(long)m * ldc + n] = v;
        }
    }
}

// ---------------------------------------------------------------------------
// Row softmax over g_attn: one block per row of length NN=1024; 4 elems/thread.
// ---------------------------------------------------------------------------
__global__ __launch_bounds__(256) void softmax_kernel(float* __restrict__ attn)
{
    float* row = attn + (long)blockIdx.x * NN;
    const int tid = threadIdx.x;
    const int wid = tid >> 5, lid = tid & 31;
    __shared__ float sred[8];

    float v[4];
    float mx = -1e30f;
    #pragma unroll
    for (int i = 0; i < 4; i++) { v[i] = row[tid + i * 256]; mx = fmaxf(mx, v[i]); }
    #pragma unroll
    for (int o = 16; o > 0; o >>= 1) mx = fmaxf(mx, __shfl_xor_sync(~0u, mx, o));
    if (lid == 0) sred[wid] = mx;
    __syncthreads();
    if (wid == 0) {
        float m2 = (lid < 8) ? sred[lid] : -1e30f;
        #pragma unroll
        for (int o = 4; o > 0; o >>= 1) m2 = fmaxf(m2, __shfl_xor_sync(~0u, m2, o));
        if (lid == 0) sred[0] = m2;
    }
    __syncthreads();
    mx = sred[0];

    float s = 0.f;
    #pragma unroll
    for (int i = 0; i < 4; i++) { v[i] = __expf(v[i] - mx); s += v[i]; }
    #pragma unroll
    for (int o = 16; o > 0; o >>= 1) s += __shfl_xor_sync(~0u, s, o);
    __syncthreads();
    if (lid == 0) sred[wid] = s;
    __syncthreads();
    if (wid == 0) {
        float t = (lid < 8) ? sred[lid] : 0.f;
        #pragma unroll
        for (int o = 4; o > 0; o >>= 1) t += __shfl_xor_sync(~0u, t, o);
        if (lid == 0) sred[0] = t;
    }
    __syncthreads();
    const float inv = 1.0f / sred[0];
    #pragma unroll
    for (int i = 0; i < 4; i++) row[tid + i * 256] = v[i] * inv;
}

// ---------------------------------------------------------------------------
extern "C" void kernel_launch(void* const* d_in, const int* in_sizes, int n_in,
                              void* d_out, int out_size)
{
    const float* x   = (const float*)d_in[0];
    const float* gns = (const float*)d_in[1];
    const float* gnb = (const float*)d_in[2];
    const float* wq  = (const float*)d_in[3];
    const float* bq  = (const float*)d_in[4];
    const float* wk  = (const float*)d_in[5];
    const float* bk  = (const float*)d_in[6];
    const float* wv  = (const float*)d_in[7];
    const float* bv  = (const float*)d_in[8];
    const float* wp  = (const float*)d_in[9];
    const float* bp  = (const float*)d_in[10];
    float* out = (float*)d_out;

    float *xn, *q, *k, *v, *attn, *o;
    cudaGetSymbolAddress((void**)&xn,   g_xn);
    cudaGetSymbolAddress((void**)&q,    g_q);
    cudaGetSymbolAddress((void**)&k,    g_k);
    cudaGetSymbolAddress((void**)&v,    g_v);
    cudaGetSymbolAddress((void**)&attn, g_attn);
    cudaGetSymbolAddress((void**)&o,    g_o);

    const long SX = (long)CC * NN;       // per-batch stride of [C,N] tensors
    const long SA = (long)NN * NN;       // per-batch stride of attn
    const float inv_sqrt_c = 1.0f / sqrtf((float)CC);

    // 1. GroupNorm
    gn_kernel<<<BB * NG, 256>>>(x, gns, gnb, xn);

    // 2. q, k, v = W @ xn + b     (M=C=512, N=1024, K=C=512)
    {
        dim3 grid(NN / 128, CC / 128, BB);
        gemm_k<false, false, 1><<<grid, 256>>>(wq, 0, xn, SX, q, SX, bq, nullptr, 0,
                                               CC, CC, NN, NN, 1.0f);
        gemm_k<false, false, 1><<<grid, 256>>>(wk, 0, xn, SX, k, SX, bk, nullptr, 0,
                                               CC, CC, NN, NN, 1.0f);
        gemm_k<false, false, 1><<<grid, 256>>>(wv, 0, xn, SX, v, SX, bv, nullptr, 0,
                                               CC, CC, NN, NN, 1.0f);
    }

    // 3. attn[i,j] = (1/sqrt(C)) * sum_c q[c,i] k[c,j]   (M=N=1024, K=512, A^T)
    {
        dim3 grid(NN / 128, NN / 128, BB);
        gemm_k<true, false, 0><<<grid, 256>>>(q, SX, k, SX, attn, SA, nullptr, nullptr, 0,
                                              CC, NN, NN, NN, inv_sqrt_c);
    }

    // 4. softmax rows
    softmax_kernel<<<BB * NN, 256>>>(attn);

    // 5. o[c,i] = sum_j v[c,j] * A[i,j]   (M=512, N=1024, K=1024, B^T)
    {
        dim3 grid(NN / 128, CC / 128, BB);
        gemm_k<false, true, 0><<<grid, 256>>>(v, SX, attn, SA, o, SX, nullptr, nullptr, 0,
                                              NN, NN, NN, NN, 1.0f);
    }

    // 6. out = wp @ o + bp + x   (residual)
    {
        dim3 grid(NN / 128, CC / 128, BB);
        gemm_k<false, false, 3><<<grid, 256>>>(wp, 0, o, SX, out, SX, bp, x, SX,
                                               CC, CC, NN, NN, 1.0f);
    }
}

// round 3
// speedup vs baseline: 1.5775x; 1.5775x over previous
#include <cuda_runtime.h>
#include <mma.h>
#include <math.h>

using namespace nvcuda;

// Problem constants
#define BB   16
#define CC   512
#define NN   1024      // H*W = 32*32
#define NG   32        // num groups
#define CPG  16        // channels per group (512/32)
#define GSZ  (CPG*NN)  // elements per group = 16384

#define TILE_M 128
#define TILE_N 128
#define TILE_K 32

// Scratch (static device globals; no runtime allocation allowed)
__device__ float g_xn  [BB*CC*NN];   // normalized x
__device__ float g_q   [BB*CC*NN];
__device__ float g_k   [BB*CC*NN];
__device__ float g_v   [BB*CC*NN];
__device__ float g_attn[BB*NN*NN];   // attention logits / probs
__device__ float g_o   [BB*CC*NN];   // attention output

// ---------------------------------------------------------------------------
// GroupNorm: one block per (batch, group).
// ---------------------------------------------------------------------------
__global__ __launch_bounds__(256) void gn_kernel(
    const float* __restrict__ x,
    const float* __restrict__ sc,
    const float* __restrict__ bi,
    float* __restrict__ out)
{
    const int bg = blockIdx.x;               // 0 .. BB*NG-1
    const float* xp = x   + (long)bg * GSZ;
    float*       op = out + (long)bg * GSZ;

    float s = 0.f, s2 = 0.f;
    for (int i = threadIdx.x; i < GSZ / 4; i += 256) {
        float4 v = ((const float4*)xp)[i];
        s  += v.x + v.y + v.z + v.w;
        s2 += v.x*v.x + v.y*v.y + v.z*v.z + v.w*v.w;
    }
    #pragma unroll
    for (int o = 16; o > 0; o >>= 1) {
        s  += __shfl_xor_sync(~0u, s,  o);
        s2 += __shfl_xor_sync(~0u, s2, o);
    }
    __shared__ float rs[8], rs2[8];
    const int wid = threadIdx.x >> 5, lid = threadIdx.x & 31;
    if (lid == 0) { rs[wid] = s; rs2[wid] = s2; }
    __syncthreads();
    if (threadIdx.x == 0) {
        float ts = 0.f, ts2 = 0.f;
        #pragma unroll
        for (int w = 0; w < 8; w++) { ts += rs[w]; ts2 += rs2[w]; }
        rs[0] = ts; rs2[0] = ts2;
    }
    __syncthreads();
    const float inv_n = 1.0f / (float)GSZ;
    const float mean  = rs[0] * inv_n;
    const float var   = rs2[0] * inv_n - mean * mean;
    const float rstd  = rsqrtf(var + 1e-5f);

    const int g = bg % NG;
    for (int i = threadIdx.x; i < GSZ / 4; i += 256) {
        const int c = g * CPG + (i >> 8);      // (i*4)/NN
        const float a = rstd * sc[c];
        const float b = bi[c] - mean * a;
        float4 v = ((const float4*)xp)[i];
        v.x = v.x * a + b; v.y = v.y * a + b;
        v.z = v.z * a + b; v.w = v.w * a + b;
        ((float4*)op)[i] = v;
    }
}

// ---------------------------------------------------------------------------
// TF32 tensor-core GEMM: C = alpha * op(A) * op(B), batched over blockIdx.z.
//   TA: A element (m,k) read as A[k*lda + m]
//   TB: B element (k,n) read as B[n*ldb + k]
// 128x128 tile, K-step 32, 8 warps each computing 64x32 via 4x2 wmma 16x16x8.
// All dims divide tile sizes for this problem; no bounds checks.
// ---------------------------------------------------------------------------
template<bool TA, bool TB>
__global__ __launch_bounds__(256) void gemm_tc(
    const float* __restrict__ Ag, long strideA,
    const float* __restrict__ Bg, long strideB,
    float*       __restrict__ Cg, long strideC,
    int K, int lda, int ldb, int ldc, float alpha)
{
    __shared__ float As[TILE_M][TILE_K + 4];   // (m,k)
    __shared__ float Bs[TILE_K][TILE_N + 4];   // (k,n)

    const float* A = Ag + blockIdx.z * strideA;
    const float* B = Bg + blockIdx.z * strideB;
    float*       C = Cg + blockIdx.z * strideC;

    const int m0 = blockIdx.y * TILE_M;
    const int n0 = blockIdx.x * TILE_N;
    const int tid = threadIdx.x;
    const int wid = tid >> 5;
    const int wm = wid & 1;     // warp row: 0..1 (64 rows each)
    const int wn = wid >> 1;    // warp col: 0..3 (32 cols each)

    wmma::fragment<wmma::accumulator, 16, 16, 8, float> acc[4][2];
    #pragma unroll
    for (int i = 0; i < 4; i++)
        #pragma unroll
        for (int j = 0; j < 2; j++)
            wmma::fill_fragment(acc[i][j], 0.0f);

    for (int k0 = 0; k0 < K; k0 += TILE_K) {
        // ---- load A tile (128 x 32) ----
        if (!TA) {
            const int t8 = tid & 7;          // k-float4
            const int mr = tid >> 3;         // 32 m per pass
            #pragma unroll
            for (int p = 0; p < 4; p++) {
                const int m = mr + p * 32;
                float4 v = *(const float4*)(A + (long)(m0 + m) * lda + k0 + t8 * 4);
                As[m][t8*4+0] = wmma::__float_to_tf32(v.x);
                As[m][t8*4+1] = wmma::__float_to_tf32(v.y);
                As[m][t8*4+2] = wmma::__float_to_tf32(v.z);
                As[m][t8*4+3] = wmma::__float_to_tf32(v.w);
            }
        } else {
            const int t32 = tid & 31;        // m-float4
            const int kr  = tid >> 5;        // 8 k per pass
            #pragma unroll
            for (int p = 0; p < 4; p++) {
                const int kk = kr + p * 8;
                float4 v = *(const float4*)(A + (long)(k0 + kk) * lda + m0 + t32 * 4);
                As[t32*4+0][kk] = wmma::__float_to_tf32(v.x);
                As[t32*4+1][kk] = wmma::__float_to_tf32(v.y);
                As[t32*4+2][kk] = wmma::__float_to_tf32(v.z);
                As[t32*4+3][kk] = wmma::__float_to_tf32(v.w);
            }
        }
        // ---- load B tile (32 x 128) ----
        if (!TB) {
            const int t32 = tid & 31;        // n-float4
            const int kr  = tid >> 5;        // 8 k per pass
            #pragma unroll
            for (int p = 0; p < 4; p++) {
                const int kk = kr + p * 8;
                float4 v = *(const float4*)(B + (long)(k0 + kk) * ldb + n0 + t32 * 4);
                Bs[kk][t32*4+0] = wmma::__float_to_tf32(v.x);
                Bs[kk][t32*4+1] = wmma::__float_to_tf32(v.y);
                Bs[kk][t32*4+2] = wmma::__float_to_tf32(v.z);
                Bs[kk][t32*4+3] = wmma::__float_to_tf32(v.w);
            }
        } else {
            const int t8 = tid & 7;          // k-float4
            const int nr = tid >> 3;         // 32 n per pass
            #pragma unroll
            for (int p = 0; p < 4; p++) {
                const int n = nr + p * 32;
                float4 v = *(const float4*)(B + (long)(n0 + n) * ldb + k0 + t8 * 4);
                Bs[t8*4+0][n] = wmma::__float_to_tf32(v.x);
                Bs[t8*4+1][n] = wmma::__float_to_tf32(v.y);
                Bs[t8*4+2][n] = wmma::__float_to_tf32(v.z);
                Bs[t8*4+3][n] = wmma::__float_to_tf32(v.w);
            }
        }
        __syncthreads();

        // ---- compute ----
        #pragma unroll
        for (int kf = 0; kf < TILE_K / 8; kf++) {
            wmma::fragment<wmma::matrix_a, 16, 16, 8, wmma::precision::tf32, wmma::row_major> af[4];
            wmma::fragment<wmma::matrix_b, 16, 16, 8, wmma::precision::tf32, wmma::row_major> bf[2];
            #pragma unroll
            for (int i = 0; i < 4; i++)
                wmma::load_matrix_sync(af[i], &As[wm*64 + i*16][kf*8], TILE_K + 4);
            #pragma unroll
            for (int j = 0; j < 2; j++)
                wmma::load_matrix_sync(bf[j], &Bs[kf*8][wn*32 + j*16], TILE_N + 4);
            #pragma unroll
            for (int i = 0; i < 4; i++)
                #pragma unroll
                for (int j = 0; j < 2; j++)
                    wmma::mma_sync(acc[i][j], af[i], bf[j], acc[i][j]);
        }
        __syncthreads();
    }

    // ---- epilogue: scale + store ----
    #pragma unroll
    for (int i = 0; i < 4; i++)
        #pragma unroll
        for (int j = 0; j < 2; j++) {
            if (alpha != 1.0f) {
                #pragma unroll
                for (int t = 0; t < acc[i][j].num_elements; t++)
                    acc[i][j].x[t] *= alpha;
            }
            wmma::store_matrix_sync(
                C + (long)(m0 + wm*64 + i*16) * ldc + n0 + wn*32 + j*16,
                acc[i][j], ldc, wmma::mem_row_major);
        }
}

// ---------------------------------------------------------------------------
// Elementwise: t[b, c, n] += bias[c]   over [BB, CC, NN] fp32, float4-wide.
// ---------------------------------------------------------------------------
__global__ __launch_bounds__(256) void bias_add_kernel(
    float* __restrict__ t, const float* __restrict__ bias)
{
    const long i = (long)blockIdx.x * 256 + threadIdx.x;   // float4 index
    const int c = (int)(i >> 8) & (CC - 1);                // NN/4 = 256 per channel
    const float b = bias[c];
    float4 v = ((float4*)t)[i];
    v.x += b; v.y += b; v.z += b; v.w += b;
    ((float4*)t)[i] = v;
}

// out += bias[c] + x  (final residual epilogue)
__global__ __launch_bounds__(256) void final_epi_kernel(
    float* __restrict__ out, const float* __restrict__ x,
    const float* __restrict__ bias)
{
    const long i = (long)blockIdx.x * 256 + threadIdx.x;
    const int c = (int)(i >> 8) & (CC - 1);
    const float b = bias[c];
    float4 v = ((float4*)out)[i];
    float4 r = ((const float4*)x)[i];
    v.x += b + r.x; v.y += b + r.y; v.z += b + r.z; v.w += b + r.w;
    ((float4*)out)[i] = v;
}

// ---------------------------------------------------------------------------
// Row softmax over g_attn: one block per row of length NN=1024.
// ---------------------------------------------------------------------------
__global__ __launch_bounds__(256) void softmax_kernel(float* __restrict__ attn)
{
    float* row = attn + (long)blockIdx.x * NN;
    const int tid = threadIdx.x;
    const int wid = tid >> 5, lid = tid & 31;
    __shared__ float sred[8];

    float4 v = ((float4*)row)[tid];
    float mx = fmaxf(fmaxf(v.x, v.y), fmaxf(v.z, v.w));
    #pragma unroll
    for (int o = 16; o > 0; o >>= 1) mx = fmaxf(mx, __shfl_xor_sync(~0u, mx, o));
    if (lid == 0) sred[wid] = mx;
    __syncthreads();
    if (wid == 0) {
        float m2 = (lid < 8) ? sred[lid] : -1e30f;
        #pragma unroll
        for (int o = 4; o > 0; o >>= 1) m2 = fmaxf(m2, __shfl_xor_sync(~0u, m2, o));
        if (lid == 0) sred[0] = m2;
    }
    __syncthreads();
    mx = sred[0];

    v.x = __expf(v.x - mx); v.y = __expf(v.y - mx);
    v.z = __expf(v.z - mx); v.w = __expf(v.w - mx);
    float s = v.x + v.y + v.z + v.w;
    #pragma unroll
    for (int o = 16; o > 0; o >>= 1) s += __shfl_xor_sync(~0u, s, o);
    __syncthreads();
    if (lid == 0) sred[wid] = s;
    __syncthreads();
    if (wid == 0) {
        float t = (lid < 8) ? sred[lid] : 0.f;
        #pragma unroll
        for (int o = 4; o > 0; o >>= 1) t += __shfl_xor_sync(~0u, t, o);
        if (lid == 0) sred[0] = t;
    }
    __syncthreads();
    const float inv = 1.0f / sred[0];
    v.x *= inv; v.y *= inv; v.z *= inv; v.w *= inv;
    ((float4*)row)[tid] = v;
}

// ---------------------------------------------------------------------------
extern "C" void kernel_launch(void* const* d_in, const int* in_sizes, int n_in,
                              void* d_out, int out_size)
{
    const float* x   = (const float*)d_in[0];
    const float* gns = (const float*)d_in[1];
    const float* gnb = (const float*)d_in[2];
    const float* wq  = (const float*)d_in[3];
    const float* bq  = (const float*)d_in[4];
    const float* wk  = (const float*)d_in[5];
    const float* bk  = (const float*)d_in[6];
    const float* wv  = (const float*)d_in[7];
    const float* bv  = (const float*)d_in[8];
    const float* wp  = (const float*)d_in[9];
    const float* bp  = (const float*)d_in[10];
    float* out = (float*)d_out;

    float *xn, *q, *k, *v, *attn, *o;
    cudaGetSymbolAddress((void**)&xn,   g_xn);
    cudaGetSymbolAddress((void**)&q,    g_q);
    cudaGetSymbolAddress((void**)&k,    g_k);
    cudaGetSymbolAddress((void**)&v,    g_v);
    cudaGetSymbolAddress((void**)&attn, g_attn);
    cudaGetSymbolAddress((void**)&o,    g_o);

    const long SX = (long)CC * NN;       // per-batch stride of [C,N] tensors
    const long SA = (long)NN * NN;       // per-batch stride of attn
    const float inv_sqrt_c = 1.0f / sqrtf((float)CC);
    const long EW_GRID = (long)BB * CC * NN / 4 / 256;   // elementwise grid

    // 1. GroupNorm
    gn_kernel<<<BB * NG, 256>>>(x, gns, gnb, xn);

    // 2. q, k, v = W @ xn (+ bias via elementwise)
    {
        dim3 grid(NN / TILE_N, CC / TILE_M, BB);
        gemm_tc<false, false><<<grid, 256>>>(wq, 0, xn, SX, q, SX, CC, CC, NN, NN, 1.0f);
        gemm_tc<false, false><<<grid, 256>>>(wk, 0, xn, SX, k, SX, CC, CC, NN, NN, 1.0f);
        gemm_tc<false, false><<<grid, 256>>>(wv, 0, xn, SX, v, SX, CC, CC, NN, NN, 1.0f);
        bias_add_kernel<<<EW_GRID, 256>>>(q, bq);
        bias_add_kernel<<<EW_GRID, 256>>>(k, bk);
        bias_add_kernel<<<EW_GRID, 256>>>(v, bv);
    }

    // 3. attn[i,j] = (1/sqrt(C)) * sum_c q[c,i] k[c,j]   (TA)
    {
        dim3 grid(NN / TILE_N, NN / TILE_M, BB);
        gemm_tc<true, false><<<grid, 256>>>(q, SX, k, SX, attn, SA, CC, NN, NN, NN, inv_sqrt_c);
    }

    // 4. softmax rows
    softmax_kernel<<<BB * NN, 256>>>(attn);

    // 5. o[c,i] = sum_j v[c,j] * A[i,j]   (TB)
    {
        dim3 grid(NN / TILE_N, CC / TILE_M, BB);
        gemm_tc<false, true><<<grid, 256>>>(v, SX, attn, SA, o, SX, NN, NN, NN, NN, 1.0f);
    }

    // 6. out = wp @ o, then out += bp + x
    {
        dim3 grid(NN / TILE_N, CC / TILE_M, BB);
        gemm_tc<false, false><<<grid, 256>>>(wp, 0, o, SX, out, SX, CC, CC, NN, NN, 1.0f);
        final_epi_kernel<<<EW_GRID, 256>>>(out, x, bp);
    }
}

// round 5
// speedup vs baseline: 2.0158x; 1.2778x over previous
#include <cuda_runtime.h>
#include <mma.h>
#include <math.h>
#include <type_traits>

using namespace nvcuda;

// Problem constants
#define BB   16
#define CC   512
#define NN   1024      // H*W = 32*32
#define NG   32        // num groups
#define CPG  16        // channels per group (512/32)
#define GSZ  (CPG*NN)  // elements per group = 16384

#define TILE_M 128
#define TILE_N 128
#define TILE_K 32
#define PAD    4

// Scratch (static device globals; no runtime allocation allowed)
__device__ float g_xn  [BB*CC*NN];
__device__ float g_q   [BB*CC*NN];
__device__ float g_k   [BB*CC*NN];
__device__ float g_v   [BB*CC*NN];
__device__ float g_attn[BB*NN*NN];
__device__ float g_o   [BB*CC*NN];

// ---------------------------------------------------------------------------
__device__ __forceinline__ void cp_async16(void* smem, const void* gmem) {
    unsigned s = (unsigned)__cvta_generic_to_shared(smem);
    asm volatile("cp.async.cg.shared.global [%0], [%1], 16;\n" :: "r"(s), "l"(gmem));
}
__device__ __forceinline__ void cp_commit() {
    asm volatile("cp.async.commit_group;\n");
}
template<int N>
__device__ __forceinline__ void cp_wait() {
    asm volatile("cp.async.wait_group %0;\n" :: "n"(N));
}

// ---------------------------------------------------------------------------
// GroupNorm: one block per (batch, group).
// ---------------------------------------------------------------------------
__global__ __launch_bounds__(256) void gn_kernel(
    const float* __restrict__ x,
    const float* __restrict__ sc,
    const float* __restrict__ bi,
    float* __restrict__ out)
{
    const int bg = blockIdx.x;
    const float* xp = x   + (long)bg * GSZ;
    float*       op = out + (long)bg * GSZ;

    float s = 0.f, s2 = 0.f;
    for (int i = threadIdx.x; i < GSZ / 4; i += 256) {
        float4 v = ((const float4*)xp)[i];
        s  += v.x + v.y + v.z + v.w;
        s2 += v.x*v.x + v.y*v.y + v.z*v.z + v.w*v.w;
    }
    #pragma unroll
    for (int o = 16; o > 0; o >>= 1) {
        s  += __shfl_xor_sync(~0u, s,  o);
        s2 += __shfl_xor_sync(~0u, s2, o);
    }
    __shared__ float rs[8], rs2[8];
    const int wid = threadIdx.x >> 5, lid = threadIdx.x & 31;
    if (lid == 0) { rs[wid] = s; rs2[wid] = s2; }
    __syncthreads();
    if (threadIdx.x == 0) {
        float ts = 0.f, ts2 = 0.f;
        #pragma unroll
        for (int w = 0; w < 8; w++) { ts += rs[w]; ts2 += rs2[w]; }
        rs[0] = ts; rs2[0] = ts2;
    }
    __syncthreads();
    const float inv_n = 1.0f / (float)GSZ;
    const float mean  = rs[0] * inv_n;
    const float var   = rs2[0] * inv_n - mean * mean;
    const float rstd  = rsqrtf(var + 1e-5f);

    const int g = bg % NG;
    for (int i = threadIdx.x; i < GSZ / 4; i += 256) {
        const int c = g * CPG + (i >> 8);
        const float a = rstd * sc[c];
        const float b = bi[c] - mean * a;
        float4 v = ((const float4*)xp)[i];
        v.x = v.x * a + b; v.y = v.y * a + b;
        v.z = v.z * a + b; v.w = v.w * a + b;
        ((float4*)op)[i] = v;
    }
}

// ---------------------------------------------------------------------------
// TF32 tensor-core GEMM, cp.async double-buffered.
//   C = alpha * op(A) * op(B), batched over blockIdx.z.
//   TA: A(m,k) = A[k*lda + m]  (stored k-major; consumed as wmma col_major)
//   TB: B(k,n) = B[n*ldb + k]  (stored n-major; consumed as wmma col_major)
// All smem staging copies are contiguous 16B cp.async in every layout case.
// fp32 bits fed directly to tf32 MMA (hardware truncates low mantissa bits).
// ---------------------------------------------------------------------------
template<bool TA, bool TB>
__global__ __launch_bounds__(256) void gemm_tc(
    const float* __restrict__ Ag, long strideA,
    const float* __restrict__ Bg, long strideB,
    float*       __restrict__ Cg, long strideC,
    int K, int lda, int ldb, int ldc, float alpha)
{
    // smem tile geometry (element strides) per layout
    constexpr int A_LD   = TA ? (TILE_M + PAD) : (TILE_K + PAD);
    constexpr int A_SIZE = TA ? TILE_K * A_LD  : TILE_M * A_LD;
    constexpr int B_LD   = TB ? (TILE_K + PAD) : (TILE_N + PAD);
    constexpr int B_SIZE = TB ? TILE_N * B_LD  : TILE_K * B_LD;

    __shared__ float As[2][A_SIZE];
    __shared__ float Bs[2][B_SIZE];

    const float* A = Ag + blockIdx.z * strideA;
    const float* B = Bg + blockIdx.z * strideB;
    float*       C = Cg + blockIdx.z * strideC;

    const int m0 = blockIdx.y * TILE_M;
    const int n0 = blockIdx.x * TILE_N;
    const int tid = threadIdx.x;
    const int wid = tid >> 5;
    const int wm = wid & 1;     // 2 warp rows  (64 m each)
    const int wn = wid >> 1;    // 4 warp cols  (32 n each)

    typedef typename std::conditional<TA, wmma::col_major, wmma::row_major>::type ALay;
    typedef typename std::conditional<TB, wmma::col_major, wmma::row_major>::type BLay;

    wmma::fragment<wmma::accumulator, 16, 16, 8, float> acc[4][2];
    #pragma unroll
    for (int i = 0; i < 4; i++)
        #pragma unroll
        for (int j = 0; j < 2; j++)
            wmma::fill_fragment(acc[i][j], 0.0f);

    // tile loader: stage s, k-offset k0
    auto load_tiles = [&](int s, int k0) {
        float* as = As[s];
        float* bs = Bs[s];
        if (!TA) {
            // As[m][k]: rows of 32 floats, 8 chunks per row
            #pragma unroll
            for (int p = 0; p < 4; p++) {
                const int c = tid + p * 256;
                const int m = c >> 3, kc = c & 7;
                cp_async16(&as[m * A_LD + kc * 4],
                           A + (long)(m0 + m) * lda + k0 + kc * 4);
            }
        } else {
            // As[k][m]: rows of 128 floats, 32 chunks per row
            #pragma unroll
            for (int p = 0; p < 4; p++) {
                const int c = tid + p * 256;
                const int kk = c >> 5, mc = c & 31;
                cp_async16(&as[kk * A_LD + mc * 4],
                           A + (long)(k0 + kk) * lda + m0 + mc * 4);
            }
        }
        if (!TB) {
            // Bs[k][n]: rows of 128 floats
            #pragma unroll
            for (int p = 0; p < 4; p++) {
                const int c = tid + p * 256;
                const int kk = c >> 5, nc = c & 31;
                cp_async16(&bs[kk * B_LD + nc * 4],
                           B + (long)(k0 + kk) * ldb + n0 + nc * 4);
            }
        } else {
            // Bs[n][k]: rows of 32 floats
            #pragma unroll
            for (int p = 0; p < 4; p++) {
                const int c = tid + p * 256;
                const int n = c >> 3, kc = c & 7;
                cp_async16(&bs[n * B_LD + kc * 4],
                           B + (long)(n0 + n) * ldb + k0 + kc * 4);
            }
        }
    };

    const int KT = K / TILE_K;
    load_tiles(0, 0);
    cp_commit();

    for (int kt = 0; kt < KT; kt++) {
        const int s = kt & 1;
        if (kt + 1 < KT) {
            load_tiles(s ^ 1, (kt + 1) * TILE_K);
            cp_commit();
            cp_wait<1>();
        } else {
            cp_wait<0>();
        }
        __syncthreads();

        const float* as = As[s];
        const float* bs = Bs[s];
        #pragma unroll
        for (int kf = 0; kf < TILE_K / 8; kf++) {
            wmma::fragment<wmma::matrix_a, 16, 16, 8, wmma::precision::tf32, ALay> af[4];
            wmma::fragment<wmma::matrix_b, 16, 16, 8, wmma::precision::tf32, BLay> bf[2];
            #pragma unroll
            for (int i = 0; i < 4; i++) {
                const float* p = TA ? &as[(kf*8) * A_LD + wm*64 + i*16]
                                    : &as[(wm*64 + i*16) * A_LD + kf*8];
                wmma::load_matrix_sync(af[i], p, A_LD);
            }
            #pragma unroll
            for (int j = 0; j < 2; j++) {
                const float* p = TB ? &bs[(wn*32 + j*16) * B_LD + kf*8]
                                    : &bs[(kf*8) * B_LD + wn*32 + j*16];
                wmma::load_matrix_sync(bf[j], p, B_LD);
            }
            #pragma unroll
            for (int i = 0; i < 4; i++)
                #pragma unroll
                for (int j = 0; j < 2; j++)
                    wmma::mma_sync(acc[i][j], af[i], bf[j], acc[i][j]);
        }
        __syncthreads();
    }

    #pragma unroll
    for (int i = 0; i < 4; i++)
        #pragma unroll
        for (int j = 0; j < 2; j++) {
            if (alpha != 1.0f) {
                #pragma unroll
                for (int t = 0; t < acc[i][j].num_elements; t++)
                    acc[i][j].x[t] *= alpha;
            }
            wmma::store_matrix_sync(
                C + (long)(m0 + wm*64 + i*16) * ldc + n0 + wn*32 + j*16,
                acc[i][j], ldc, wmma::mem_row_major);
        }
}

// ---------------------------------------------------------------------------
__global__ __launch_bounds__(256) void bias_add_kernel(
    float* __restrict__ t, const float* __restrict__ bias)
{
    const long i = (long)blockIdx.x * 256 + threadIdx.x;
    const int c = (int)(i >> 8) & (CC - 1);
    const float b = bias[c];
    float4 v = ((float4*)t)[i];
    v.x += b; v.y += b; v.z += b; v.w += b;
    ((float4*)t)[i] = v;
}

__global__ __launch_bounds__(256) void final_epi_kernel(
    float* __restrict__ out, const float* __restrict__ x,
    const float* __restrict__ bias)
{
    const long i = (long)blockIdx.x * 256 + threadIdx.x;
    const int c = (int)(i >> 8) & (CC - 1);
    const float b = bias[c];
    float4 v = ((float4*)out)[i];
    float4 r = ((const float4*)x)[i];
    v.x += b + r.x; v.y += b + r.y; v.z += b + r.z; v.w += b + r.w;
    ((float4*)out)[i] = v;
}

// ---------------------------------------------------------------------------
__global__ __launch_bounds__(256) void softmax_kernel(float* __restrict__ attn)
{
    float* row = attn + (long)blockIdx.x * NN;
    const int tid = threadIdx.x;
    const int wid = tid >> 5, lid = tid & 31;
    __shared__ float sred[8];

    float4 v = ((float4*)row)[tid];
    float mx = fmaxf(fmaxf(v.x, v.y), fmaxf(v.z, v.w));
    #pragma unroll
    for (int o = 16; o > 0; o >>= 1) mx = fmaxf(mx, __shfl_xor_sync(~0u, mx, o));
    if (lid == 0) sred[wid] = mx;
    __syncthreads();
    if (wid == 0) {
        float m2 = (lid < 8) ? sred[lid] : -1e30f;
        #pragma unroll
        for (int o = 4; o > 0; o >>= 1) m2 = fmaxf(m2, __shfl_xor_sync(~0u, m2, o));
        if (lid == 0) sred[0] = m2;
    }
    __syncthreads();
    mx = sred[0];

    v.x = __expf(v.x - mx); v.y = __expf(v.y - mx);
    v.z = __expf(v.z - mx); v.w = __expf(v.w - mx);
    float s = v.x + v.y + v.z + v.w;
    #pragma unroll
    for (int o = 16; o > 0; o >>= 1) s += __shfl_xor_sync(~0u, s, o);
    __syncthreads();
    if (lid == 0) sred[wid] = s;
    __syncthreads();
    if (wid == 0) {
        float t = (lid < 8) ? sred[lid] : 0.f;
        #pragma unroll
        for (int o = 4; o > 0; o >>= 1) t += __shfl_xor_sync(~0u, t, o);
        if (lid == 0) sred[0] = t;
    }
    __syncthreads();
    const float inv = 1.0f / sred[0];
    v.x *= inv; v.y *= inv; v.z *= inv; v.w *= inv;
    ((float4*)row)[tid] = v;
}

// ---------------------------------------------------------------------------
extern "C" void kernel_launch(void* const* d_in, const int* in_sizes, int n_in,
                              void* d_out, int out_size)
{
    const float* x   = (const float*)d_in[0];
    const float* gns = (const float*)d_in[1];
    const float* gnb = (const float*)d_in[2];
    const float* wq  = (const float*)d_in[3];
    const float* bq  = (const float*)d_in[4];
    const float* wk  = (const float*)d_in[5];
    const float* bk  = (const float*)d_in[6];
    const float* wv  = (const float*)d_in[7];
    const float* bv  = (const float*)d_in[8];
    const float* wp  = (const float*)d_in[9];
    const float* bp  = (const float*)d_in[10];
    float* out = (float*)d_out;

    float *xn, *q, *k, *v, *attn, *o;
    cudaGetSymbolAddress((void**)&xn,   g_xn);
    cudaGetSymbolAddress((void**)&q,    g_q);
    cudaGetSymbolAddress((void**)&k,    g_k);
    cudaGetSymbolAddress((void**)&v,    g_v);
    cudaGetSymbolAddress((void**)&attn, g_attn);
    cudaGetSymbolAddress((void**)&o,    g_o);

    const long SX = (long)CC * NN;
    const long SA = (long)NN * NN;
    const float inv_sqrt_c = 1.0f / sqrtf((float)CC);
    const long EW_GRID = (long)BB * CC * NN / 4 / 256;

    // 1. GroupNorm
    gn_kernel<<<BB * NG, 256>>>(x, gns, gnb, xn);

    // 2. q, k, v = W @ xn (+ bias via elementwise)
    {
        dim3 grid(NN / TILE_N, CC / TILE_M, BB);
        gemm_tc<false, false><<<grid, 256>>>(wq, 0, xn, SX, q, SX, CC, CC, NN, NN, 1.0f);
        gemm_tc<false, false><<<grid, 256>>>(wk, 0, xn, SX, k, SX, CC, CC, NN, NN, 1.0f);
        gemm_tc<false, false><<<grid, 256>>>(wv, 0, xn, SX, v, SX, CC, CC, NN, NN, 1.0f);
        bias_add_kernel<<<EW_GRID, 256>>>(q, bq);
        bias_add_kernel<<<EW_GRID, 256>>>(k, bk);
        bias_add_kernel<<<EW_GRID, 256>>>(v, bv);
    }

    // 3. attn[i,j] = (1/sqrt(C)) * sum_c q[c,i] k[c,j]   (TA)
    {
        dim3 grid(NN / TILE_N, NN / TILE_M, BB);
        gemm_tc<true, false><<<grid, 256>>>(q, SX, k, SX, attn, SA, CC, NN, NN, NN, inv_sqrt_c);
    }

    // 4. softmax rows
    softmax_kernel<<<BB * NN, 256>>>(attn);

    // 5. o[c,i] = sum_j v[c,j] * A[i,j]   (TB)
    {
        dim3 grid(NN / TILE_N, CC / TILE_M, BB);
        gemm_tc<false, true><<<grid, 256>>>(v, SX, attn, SA, o, SX, NN, NN, NN, NN, 1.0f);
    }

    // 6. out = wp @ o, then out += bp + x
    {
        dim3 grid(NN / TILE_N, CC / TILE_M, BB);
        gemm_tc<false, false><<<grid, 256>>>(wp, 0, o, SX, out, SX, CC, CC, NN, NN, 1.0f);
        final_epi_kernel<<<EW_GRID, 256>>>(out, x, bp);
    }
}

// round 6
// speedup vs baseline: 2.1715x; 1.0773x over previous
#include <cuda_runtime.h>
#include <mma.h>
#include <math.h>
#include <type_traits>

using namespace nvcuda;

// Problem constants
#define BB   16
#define CC   512
#define NN   1024
#define NG   32
#define CPG  16
#define GSZ  (CPG*NN)

#define TILE_M 128
#define TILE_N 128
#define TILE_K 32
#define PAD    4
#define STAGES 3

// Scratch (static device globals; no runtime allocation allowed)
__device__ float g_xn  [BB*CC*NN];
__device__ float g_q   [BB*CC*NN];
__device__ float g_k   [BB*CC*NN];
__device__ float g_v   [BB*CC*NN];
__device__ float g_attn[BB*NN*NN];
__device__ float g_o   [BB*CC*NN];

// ---------------------------------------------------------------------------
__device__ __forceinline__ void cp_async16(void* smem, const void* gmem) {
    unsigned s = (unsigned)__cvta_generic_to_shared(smem);
    asm volatile("cp.async.cg.shared.global [%0], [%1], 16;\n" :: "r"(s), "l"(gmem));
}
__device__ __forceinline__ void cp_commit() {
    asm volatile("cp.async.commit_group;\n");
}
template<int N>
__device__ __forceinline__ void cp_wait() {
    asm volatile("cp.async.wait_group %0;\n" :: "n"(N));
}

// ---------------------------------------------------------------------------
// GroupNorm
// ---------------------------------------------------------------------------
__global__ __launch_bounds__(256) void gn_kernel(
    const float* __restrict__ x,
    const float* __restrict__ sc,
    const float* __restrict__ bi,
    float* __restrict__ out)
{
    const int bg = blockIdx.x;
    const float* xp = x   + (long)bg * GSZ;
    float*       op = out + (long)bg * GSZ;

    float s = 0.f, s2 = 0.f;
    for (int i = threadIdx.x; i < GSZ / 4; i += 256) {
        float4 v = ((const float4*)xp)[i];
        s  += v.x + v.y + v.z + v.w;
        s2 += v.x*v.x + v.y*v.y + v.z*v.z + v.w*v.w;
    }
    #pragma unroll
    for (int o = 16; o > 0; o >>= 1) {
        s  += __shfl_xor_sync(~0u, s,  o);
        s2 += __shfl_xor_sync(~0u, s2, o);
    }
    __shared__ float rs[8], rs2[8];
    const int wid = threadIdx.x >> 5, lid = threadIdx.x & 31;
    if (lid == 0) { rs[wid] = s; rs2[wid] = s2; }
    __syncthreads();
    if (threadIdx.x == 0) {
        float ts = 0.f, ts2 = 0.f;
        #pragma unroll
        for (int w = 0; w < 8; w++) { ts += rs[w]; ts2 += rs2[w]; }
        rs[0] = ts; rs2[0] = ts2;
    }
    __syncthreads();
    const float inv_n = 1.0f / (float)GSZ;
    const float mean  = rs[0] * inv_n;
    const float var   = rs2[0] * inv_n - mean * mean;
    const float rstd  = rsqrtf(var + 1e-5f);

    const int g = bg % NG;
    for (int i = threadIdx.x; i < GSZ / 4; i += 256) {
        const int c = g * CPG + (i >> 8);
        const float a = rstd * sc[c];
        const float b = bi[c] - mean * a;
        float4 v = ((const float4*)xp)[i];
        v.x = v.x * a + b; v.y = v.y * a + b;
        v.z = v.z * a + b; v.w = v.w * a + b;
        ((float4*)op)[i] = v;
    }
}

// ---------------------------------------------------------------------------
// TF32 tensor-core GEMM, 3-stage cp.async ring, ONE sync per K-step.
//   C = alpha * op(A) * op(B), batched over blockIdx.z.
//   TA: A(m,k) = A[k*lda + m]  (k-major storage, consumed col_major)
//   TB: B(k,n) = B[n*ldb + k]  (n-major storage, consumed col_major)
// __launch_bounds__(256, 2): cap regs at 128 so 2 CTAs co-reside per SM.
// ---------------------------------------------------------------------------
template<bool TA, bool TB>
__global__ __launch_bounds__(256, 2) void gemm_tc(
    const float* __restrict__ Ag, long strideA,
    const float* __restrict__ Bg, long strideB,
    float*       __restrict__ Cg, long strideC,
    int K, int lda, int ldb, int ldc, float alpha)
{
    constexpr int A_LD   = TA ? (TILE_M + PAD) : (TILE_K + PAD);
    constexpr int A_SIZE = TA ? TILE_K * A_LD  : TILE_M * A_LD;
    constexpr int B_LD   = TB ? (TILE_K + PAD) : (TILE_N + PAD);
    constexpr int B_SIZE = TB ? TILE_N * B_LD  : TILE_K * B_LD;

    __shared__ float As[STAGES][A_SIZE];
    __shared__ float Bs[STAGES][B_SIZE];

    const float* A = Ag + blockIdx.z * strideA;
    const float* B = Bg + blockIdx.z * strideB;
    float*       C = Cg + blockIdx.z * strideC;

    const int m0 = blockIdx.y * TILE_M;
    const int n0 = blockIdx.x * TILE_N;
    const int tid = threadIdx.x;
    const int wid = tid >> 5;
    const int wm = wid & 1;
    const int wn = wid >> 1;

    typedef typename std::conditional<TA, wmma::col_major, wmma::row_major>::type ALay;
    typedef typename std::conditional<TB, wmma::col_major, wmma::row_major>::type BLay;

    wmma::fragment<wmma::accumulator, 16, 16, 8, float> acc[4][2];
    #pragma unroll
    for (int i = 0; i < 4; i++)
        #pragma unroll
        for (int j = 0; j < 2; j++)
            wmma::fill_fragment(acc[i][j], 0.0f);

    auto load_tiles = [&](int s, int k0) {
        float* as = As[s];
        float* bs = Bs[s];
        if (!TA) {
            #pragma unroll
            for (int p = 0; p < 4; p++) {
                const int c = tid + p * 256;
                const int m = c >> 3, kc = c & 7;
                cp_async16(&as[m * A_LD + kc * 4],
                           A + (long)(m0 + m) * lda + k0 + kc * 4);
            }
        } else {
            #pragma unroll
            for (int p = 0; p < 4; p++) {
                const int c = tid + p * 256;
                const int kk = c >> 5, mc = c & 31;
                cp_async16(&as[kk * A_LD + mc * 4],
                           A + (long)(k0 + kk) * lda + m0 + mc * 4);
            }
        }
        if (!TB) {
            #pragma unroll
            for (int p = 0; p < 4; p++) {
                const int c = tid + p * 256;
                const int kk = c >> 5, nc = c & 31;
                cp_async16(&bs[kk * B_LD + nc * 4],
                           B + (long)(k0 + kk) * ldb + n0 + nc * 4);
            }
        } else {
            #pragma unroll
            for (int p = 0; p < 4; p++) {
                const int c = tid + p * 256;
                const int n = c >> 3, kc = c & 7;
                cp_async16(&bs[n * B_LD + kc * 4],
                           B + (long)(n0 + n) * ldb + k0 + kc * 4);
            }
        }
    };

    const int KT = K / TILE_K;
    // prologue: prefetch tiles 0 and 1
    load_tiles(0, 0);
    cp_commit();
    if (KT > 1) { load_tiles(1, TILE_K); }
    cp_commit();

    int s = 0;
    for (int kt = 0; kt < KT; kt++) {
        if (kt == KT - 1) cp_wait<0>(); else cp_wait<1>();
        __syncthreads();   // single barrier: data for stage s ready, and all
                           // warps past prior compute so stage (kt+2)%3 is free

        // prefetch tile kt+2 into the stage nobody is touching
        if (kt + 2 < KT) {
            int sn = s + 2; if (sn >= STAGES) sn -= STAGES;
            load_tiles(sn, (kt + 2) * TILE_K);
        }
        cp_commit();

        const float* as = As[s];
        const float* bs = Bs[s];
        #pragma unroll
        for (int kf = 0; kf < TILE_K / 8; kf++) {
            wmma::fragment<wmma::matrix_a, 16, 16, 8, wmma::precision::tf32, ALay> af[4];
            wmma::fragment<wmma::matrix_b, 16, 16, 8, wmma::precision::tf32, BLay> bf[2];
            #pragma unroll
            for (int i = 0; i < 4; i++) {
                const float* p = TA ? &as[(kf*8) * A_LD + wm*64 + i*16]
                                    : &as[(wm*64 + i*16) * A_LD + kf*8];
                wmma::load_matrix_sync(af[i], p, A_LD);
            }
            #pragma unroll
            for (int j = 0; j < 2; j++) {
                const float* p = TB ? &bs[(wn*32 + j*16) * B_LD + kf*8]
                                    : &bs[(kf*8) * B_LD + wn*32 + j*16];
                wmma::load_matrix_sync(bf[j], p, B_LD);
            }
            #pragma unroll
            for (int i = 0; i < 4; i++)
                #pragma unroll
                for (int j = 0; j < 2; j++)
                    wmma::mma_sync(acc[i][j], af[i], bf[j], acc[i][j]);
        }
        if (++s >= STAGES) s = 0;
    }

    #pragma unroll
    for (int i = 0; i < 4; i++)
        #pragma unroll
        for (int j = 0; j < 2; j++) {
            if (alpha != 1.0f) {
                #pragma unroll
                for (int t = 0; t < acc[i][j].num_elements; t++)
                    acc[i][j].x[t] *= alpha;
            }
            wmma::store_matrix_sync(
                C + (long)(m0 + wm*64 + i*16) * ldc + n0 + wn*32 + j*16,
                acc[i][j], ldc, wmma::mem_row_major);
        }
}

// ---------------------------------------------------------------------------
__global__ __launch_bounds__(256) void bias_add_kernel(
    float* __restrict__ t, const float* __restrict__ bias)
{
    const long i = (long)blockIdx.x * 256 + threadIdx.x;
    const int c = (int)(i >> 8) & (CC - 1);
    const float b = bias[c];
    float4 v = ((float4*)t)[i];
    v.x += b; v.y += b; v.z += b; v.w += b;
    ((float4*)t)[i] = v;
}

__global__ __launch_bounds__(256) void final_epi_kernel(
    float* __restrict__ out, const float* __restrict__ x,
    const float* __restrict__ bias)
{
    const long i = (long)blockIdx.x * 256 + threadIdx.x;
    const int c = (int)(i >> 8) & (CC - 1);
    const float b = bias[c];
    float4 v = ((float4*)out)[i];
    float4 r = ((const float4*)x)[i];
    v.x += b + r.x; v.y += b + r.y; v.z += b + r.z; v.w += b + r.w;
    ((float4*)out)[i] = v;
}

// ---------------------------------------------------------------------------
__global__ __launch_bounds__(256) void softmax_kernel(float* __restrict__ attn)
{
    float* row = attn + (long)blockIdx.x * NN;
    const int tid = threadIdx.x;
    const int wid = tid >> 5, lid = tid & 31;
    __shared__ float sred[8];

    float4 v = ((float4*)row)[tid];
    float mx = fmaxf(fmaxf(v.x, v.y), fmaxf(v.z, v.w));
    #pragma unroll
    for (int o = 16; o > 0; o >>= 1) mx = fmaxf(mx, __shfl_xor_sync(~0u, mx, o));
    if (lid == 0) sred[wid] = mx;
    __syncthreads();
    if (wid == 0) {
        float m2 = (lid < 8) ? sred[lid] : -1e30f;
        #pragma unroll
        for (int o = 4; o > 0; o >>= 1) m2 = fmaxf(m2, __shfl_xor_sync(~0u, m2, o));
        if (lid == 0) sred[0] = m2;
    }
    __syncthreads();
    mx = sred[0];

    v.x = __expf(v.x - mx); v.y = __expf(v.y - mx);
    v.z = __expf(v.z - mx); v.w = __expf(v.w - mx);
    float s = v.x + v.y + v.z + v.w;
    #pragma unroll
    for (int o = 16; o > 0; o >>= 1) s += __shfl_xor_sync(~0u, s, o);
    __syncthreads();
    if (lid == 0) sred[wid] = s;
    __syncthreads();
    if (wid == 0) {
        float t = (lid < 8) ? sred[lid] : 0.f;
        #pragma unroll
        for (int o = 4; o > 0; o >>= 1) t += __shfl_xor_sync(~0u, t, o);
        if (lid == 0) sred[0] = t;
    }
    __syncthreads();
    const float inv = 1.0f / sred[0];
    v.x *= inv; v.y *= inv; v.z *= inv; v.w *= inv;
    ((float4*)row)[tid] = v;
}

// ---------------------------------------------------------------------------
extern "C" void kernel_launch(void* const* d_in, const int* in_sizes, int n_in,
                              void* d_out, int out_size)
{
    const float* x   = (const float*)d_in[0];
    const float* gns = (const float*)d_in[1];
    const float* gnb = (const float*)d_in[2];
    const float* wq  = (const float*)d_in[3];
    const float* bq  = (const float*)d_in[4];
    const float* wk  = (const float*)d_in[5];
    const float* bk  = (const float*)d_in[6];
    const float* wv  = (const float*)d_in[7];
    const float* bv  = (const float*)d_in[8];
    const float* wp  = (const float*)d_in[9];
    const float* bp  = (const float*)d_in[10];
    float* out = (float*)d_out;

    float *xn, *q, *k, *v, *attn, *o;
    cudaGetSymbolAddress((void**)&xn,   g_xn);
    cudaGetSymbolAddress((void**)&q,    g_q);
    cudaGetSymbolAddress((void**)&k,    g_k);
    cudaGetSymbolAddress((void**)&v,    g_v);
    cudaGetSymbolAddress((void**)&attn, g_attn);
    cudaGetSymbolAddress((void**)&o,    g_o);

    const long SX = (long)CC * NN;
    const long SA = (long)NN * NN;
    const float inv_sqrt_c = 1.0f / sqrtf((float)CC);
    const long EW_GRID = (long)BB * CC * NN / 4 / 256;

    // 1. GroupNorm
    gn_kernel<<<BB * NG, 256>>>(x, gns, gnb, xn);

    // 2. q, k, v = W @ xn (+ bias via elementwise)
    {
        dim3 grid(NN / TILE_N, CC / TILE_M, BB);
        gemm_tc<false, false><<<grid, 256>>>(wq, 0, xn, SX, q, SX, CC, CC, NN, NN, 1.0f);
        gemm_tc<false, false><<<grid, 256>>>(wk, 0, xn, SX, k, SX, CC, CC, NN, NN, 1.0f);
        gemm_tc<false, false><<<grid, 256>>>(wv, 0, xn, SX, v, SX, CC, CC, NN, NN, 1.0f);
        bias_add_kernel<<<EW_GRID, 256>>>(q, bq);
        bias_add_kernel<<<EW_GRID, 256>>>(k, bk);
        bias_add_kernel<<<EW_GRID, 256>>>(v, bv);
    }

    // 3. attn[i,j] = (1/sqrt(C)) * sum_c q[c,i] k[c,j]   (TA)
    {
        dim3 grid(NN / TILE_N, NN / TILE_M, BB);
        gemm_tc<true, false><<<grid, 256>>>(q, SX, k, SX, attn, SA, CC, NN, NN, NN, inv_sqrt_c);
    }

    // 4. softmax rows
    softmax_kernel<<<BB * NN, 256>>>(attn);

    // 5. o[c,i] = sum_j v[c,j] * A[i,j]   (TB)
    {
        dim3 grid(NN / TILE_N, CC / TILE_M, BB);
        gemm_tc<false, true><<<grid, 256>>>(v, SX, attn, SA, o, SX, NN, NN, NN, NN, 1.0f);
    }

    // 6. out = wp @ o, then out += bp + x
    {
        dim3 grid(NN / TILE_N, CC / TILE_M, BB);
        gemm_tc<false, false><<<grid, 256>>>(wp, 0, o, SX, out, SX, CC, CC, NN, NN, 1.0f);
        final_epi_kernel<<<EW_GRID, 256>>>(out, x, bp);
    }
}

// round 10
// speedup vs baseline: 2.2022x; 1.0141x over previous
#include <cuda_runtime.h>
#include <mma.h>
#include <math.h>
#include <type_traits>

using namespace nvcuda;

// Problem constants
#define BB   16
#define CC   512
#define NN   1024
#define NG   32
#define CPG  16
#define GSZ  (CPG*NN)

#define TILE_M 64
#define TILE_N 128
#define TILE_K 32
#define PAD    4

// Scratch (static device globals; no runtime allocation allowed)
__device__ float g_xn  [BB*CC*NN];
__device__ float g_q   [BB*CC*NN];
__device__ float g_k   [BB*CC*NN];
__device__ float g_v   [BB*CC*NN];
__device__ float g_attn[BB*NN*NN];
__device__ float g_o   [BB*CC*NN];

// ---------------------------------------------------------------------------
__device__ __forceinline__ void cp_async16(void* smem, const void* gmem) {
    unsigned s = (unsigned)__cvta_generic_to_shared(smem);
    asm volatile("cp.async.cg.shared.global [%0], [%1], 16;\n" :: "r"(s), "l"(gmem));
}
__device__ __forceinline__ void cp_commit() {
    asm volatile("cp.async.commit_group;\n");
}
template<int N>
__device__ __forceinline__ void cp_wait() {
    asm volatile("cp.async.wait_group %0;\n" :: "n"(N));
}

// ---------------------------------------------------------------------------
// GroupNorm
// ---------------------------------------------------------------------------
__global__ __launch_bounds__(256) void gn_kernel(
    const float* __restrict__ x,
    const float* __restrict__ sc,
    const float* __restrict__ bi,
    float* __restrict__ out)
{
    const int bg = blockIdx.x;
    const float* xp = x   + (long)bg * GSZ;
    float*       op = out + (long)bg * GSZ;

    float s = 0.f, s2 = 0.f;
    for (int i = threadIdx.x; i < GSZ / 4; i += 256) {
        float4 v = ((const float4*)xp)[i];
        s  += v.x + v.y + v.z + v.w;
        s2 += v.x*v.x + v.y*v.y + v.z*v.z + v.w*v.w;
    }
    #pragma unroll
    for (int o = 16; o > 0; o >>= 1) {
        s  += __shfl_xor_sync(~0u, s,  o);
        s2 += __shfl_xor_sync(~0u, s2, o);
    }
    __shared__ float rs[8], rs2[8];
    const int wid = threadIdx.x >> 5, lid = threadIdx.x & 31;
    if (lid == 0) { rs[wid] = s; rs2[wid] = s2; }
    __syncthreads();
    if (threadIdx.x == 0) {
        float ts = 0.f, ts2 = 0.f;
        #pragma unroll
        for (int w = 0; w < 8; w++) { ts += rs[w]; ts2 += rs2[w]; }
        rs[0] = ts; rs2[0] = ts2;
    }
    __syncthreads();
    const float inv_n = 1.0f / (float)GSZ;
    const float mean  = rs[0] * inv_n;
    const float var   = rs2[0] * inv_n - mean * mean;
    const float rstd  = rsqrtf(var + 1e-5f);

    const int g = bg % NG;
    for (int i = threadIdx.x; i < GSZ / 4; i += 256) {
        const int c = g * CPG + (i >> 8);
        const float a = rstd * sc[c];
        const float b = bi[c] - mean * a;
        float4 v = ((const float4*)xp)[i];
        v.x = v.x * a + b; v.y = v.y * a + b;
        v.z = v.z * a + b; v.w = v.w * a + b;
        ((float4*)op)[i] = v;
    }
}

// ---------------------------------------------------------------------------
// TF32 tensor-core GEMM. 64x128 block tile, 8 warps of 32x32, 2-stage
// cp.async ring, ONE barrier per K-step, 3 CTAs/SM.
//   C = alpha * op(A) * op(B), batched over blockIdx.z.
//   TA: A(m,k) = A[k*lda + m]   TB: B(k,n) = B[n*ldb + k]
//   QKV: blockIdx.z = sel*BB + b; A/C selected from {0,1,2} by sel.
// ---------------------------------------------------------------------------
template<bool TA, bool TB, bool QKV>
struct SmemCfg {
    static constexpr int A_LD   = TA ? (TILE_M + PAD) : (TILE_K + PAD);
    static constexpr int A_SIZE = TA ? TILE_K * A_LD  : TILE_M * A_LD;
    static constexpr int B_LD   = TB ? (TILE_K + PAD) : (TILE_N + PAD);
    static constexpr int B_SIZE = TB ? TILE_N * B_LD  : TILE_K * B_LD;
    static constexpr int BYTES  = (2 * A_SIZE + 2 * B_SIZE) * 4;
};

template<bool TA, bool TB, bool QKV>
__global__ __launch_bounds__(256, 3) void gemm_tc(
    const float* __restrict__ A0, const float* __restrict__ A1,
    const float* __restrict__ A2, long strideA,
    const float* __restrict__ Bg, long strideB,
    float* __restrict__ C0, float* __restrict__ C1, float* __restrict__ C2,
    long strideC,
    int K, int lda, int ldb, int ldc, float alpha)
{
    using Cfg = SmemCfg<TA, TB, QKV>;
    constexpr int A_LD = Cfg::A_LD, A_SIZE = Cfg::A_SIZE;
    constexpr int B_LD = Cfg::B_LD, B_SIZE = Cfg::B_SIZE;

    extern __shared__ float smem[];
    float* AsBase = smem;                    // [2][A_SIZE]
    float* BsBase = smem + 2 * A_SIZE;       // [2][B_SIZE]

    const int zz  = blockIdx.z;
    const int b   = QKV ? (zz & (BB - 1)) : zz;
    const int sel = QKV ? (zz >> 4) : 0;
    const float* A = (sel == 0 ? A0 : (sel == 1 ? A1 : A2)) + b * strideA;
    const float* B = Bg + b * strideB;
    float*       C = (sel == 0 ? C0 : (sel == 1 ? C1 : C2)) + b * strideC;

    const int m0 = blockIdx.y * TILE_M;
    const int n0 = blockIdx.x * TILE_N;
    const int tid = threadIdx.x;
    const int wid = tid >> 5;
    const int wm = wid >> 2;    // 2 warp rows (32 m each)
    const int wn = wid & 3;     // 4 warp cols (32 n each)

    typedef typename std::conditional<TA, wmma::col_major, wmma::row_major>::type ALay;
    typedef typename std::conditional<TB, wmma::col_major, wmma::row_major>::type BLay;

    wmma::fragment<wmma::accumulator, 16, 16, 8, float> acc[2][2];
    #pragma unroll
    for (int i = 0; i < 2; i++)
        #pragma unroll
        for (int j = 0; j < 2; j++)
            wmma::fill_fragment(acc[i][j], 0.0f);

    auto load_tiles = [&](int s, int k0) {
        float* as = AsBase + s * A_SIZE;
        float* bs = BsBase + s * B_SIZE;
        if (!TA) {
            #pragma unroll
            for (int p = 0; p < 2; p++) {
                const int c = tid + p * 256;
                const int m = c >> 3, kc = c & 7;
                cp_async16(&as[m * A_LD + kc * 4],
                           A + (long)(m0 + m) * lda + k0 + kc * 4);
            }
        } else {
            #pragma unroll
            for (int p = 0; p < 2; p++) {
                const int c = tid + p * 256;
                const int kk = c >> 4, mc = c & 15;
                cp_async16(&as[kk * A_LD + mc * 4],
                           A + (long)(k0 + kk) * lda + m0 + mc * 4);
            }
        }
        if (!TB) {
            #pragma unroll
            for (int p = 0; p < 4; p++) {
                const int c = tid + p * 256;
                const int kk = c >> 5, nc = c & 31;
                cp_async16(&bs[kk * B_LD + nc * 4],
                           B + (long)(k0 + kk) * ldb + n0 + nc * 4);
            }
        } else {
            #pragma unroll
            for (int p = 0; p < 4; p++) {
                const int c = tid + p * 256;
                const int n = c >> 3, kc = c & 7;
                cp_async16(&bs[n * B_LD + kc * 4],
                           B + (long)(n0 + n) * ldb + k0 + kc * 4);
            }
        }
    };

    const int KT = K / TILE_K;
    load_tiles(0, 0);
    cp_commit();

    for (int kt = 0; kt < KT; kt++) {
        const int s = kt & 1;
        cp_wait<0>();
        __syncthreads();   // stage s landed; all warps done with stage s^1

        if (kt + 1 < KT) {
            load_tiles(s ^ 1, (kt + 1) * TILE_K);   // overlaps compute below
            cp_commit();
        }

        const float* as = AsBase + s * A_SIZE;
        const float* bs = BsBase + s * B_SIZE;
        #pragma unroll
        for (int kf = 0; kf < TILE_K / 8; kf++) {
            wmma::fragment<wmma::matrix_a, 16, 16, 8, wmma::precision::tf32, ALay> af[2];
            wmma::fragment<wmma::matrix_b, 16, 16, 8, wmma::precision::tf32, BLay> bf[2];
            #pragma unroll
            for (int i = 0; i < 2; i++) {
                const float* p = TA ? &as[(kf*8) * A_LD + wm*32 + i*16]
                                    : &as[(wm*32 + i*16) * A_LD + kf*8];
                wmma::load_matrix_sync(af[i], p, A_LD);
            }
            #pragma unroll
            for (int j = 0; j < 2; j++) {
                const float* p = TB ? &bs[(wn*32 + j*16) * B_LD + kf*8]
                                    : &bs[(kf*8) * B_LD + wn*32 + j*16];
                wmma::load_matrix_sync(bf[j], p, B_LD);
            }
            #pragma unroll
            for (int i = 0; i < 2; i++)
                #pragma unroll
                for (int j = 0; j < 2; j++)
                    wmma::mma_sync(acc[i][j], af[i], bf[j], acc[i][j]);
        }
    }

    #pragma unroll
    for (int i = 0; i < 2; i++)
        #pragma unroll
        for (int j = 0; j < 2; j++) {
            if (alpha != 1.0f) {
                #pragma unroll
                for (int t = 0; t < acc[i][j].num_elements; t++)
                    acc[i][j].x[t] *= alpha;
            }
            wmma::store_matrix_sync(
                C + (long)(m0 + wm*32 + i*16) * ldc + n0 + wn*32 + j*16,
                acc[i][j], ldc, wmma::mem_row_major);
        }
}

// ---------------------------------------------------------------------------
// Elementwise epilogues
// ---------------------------------------------------------------------------
__global__ __launch_bounds__(256) void bias3_kernel(
    float* __restrict__ q, float* __restrict__ k, float* __restrict__ v,
    const float* __restrict__ bq, const float* __restrict__ bk,
    const float* __restrict__ bv)
{
    const long i = (long)blockIdx.x * 256 + threadIdx.x;
    const int c = (int)(i >> 8) & (CC - 1);
    {
        const float b = bq[c];
        float4 t = ((float4*)q)[i];
        t.x += b; t.y += b; t.z += b; t.w += b;
        ((float4*)q)[i] = t;
    }
    {
        const float b = bk[c];
        float4 t = ((float4*)k)[i];
        t.x += b; t.y += b; t.z += b; t.w += b;
        ((float4*)k)[i] = t;
    }
    {
        const float b = bv[c];
        float4 t = ((float4*)v)[i];
        t.x += b; t.y += b; t.z += b; t.w += b;
        ((float4*)v)[i] = t;
    }
}

__global__ __launch_bounds__(256) void final_epi_kernel(
    float* __restrict__ out, const float* __restrict__ x,
    const float* __restrict__ bias)
{
    const long i = (long)blockIdx.x * 256 + threadIdx.x;
    const int c = (int)(i >> 8) & (CC - 1);
    const float b = bias[c];
    float4 v = ((float4*)out)[i];
    float4 r = ((const float4*)x)[i];
    v.x += b + r.x; v.y += b + r.y; v.z += b + r.z; v.w += b + r.w;
    ((float4*)out)[i] = v;
}

// ---------------------------------------------------------------------------
__global__ __launch_bounds__(256) void softmax_kernel(float* __restrict__ attn)
{
    float* row = attn + (long)blockIdx.x * NN;
    const int tid = threadIdx.x;
    const int wid = tid >> 5, lid = tid & 31;
    __shared__ float sred[8];

    float4 v = ((float4*)row)[tid];
    float mx = fmaxf(fmaxf(v.x, v.y), fmaxf(v.z, v.w));
    #pragma unroll
    for (int o = 16; o > 0; o >>= 1) mx = fmaxf(mx, __shfl_xor_sync(~0u, mx, o));
    if (lid == 0) sred[wid] = mx;
    __syncthreads();
    if (wid == 0) {
        float m2 = (lid < 8) ? sred[lid] : -1e30f;
        #pragma unroll
        for (int o = 4; o > 0; o >>= 1) m2 = fmaxf(m2, __shfl_xor_sync(~0u, m2, o));
        if (lid == 0) sred[0] = m2;
    }
    __syncthreads();
    mx = sred[0];

    v.x = __expf(v.x - mx); v.y = __expf(v.y - mx);
    v.z = __expf(v.z - mx); v.w = __expf(v.w - mx);
    float s = v.x + v.y + v.z + v.w;
    #pragma unroll
    for (int o = 16; o > 0; o >>= 1) s += __shfl_xor_sync(~0u, s, o);
    __syncthreads();
    if (lid == 0) sred[wid] = s;
    __syncthreads();
    if (wid == 0) {
        float t = (lid < 8) ? sred[lid] : 0.f;
        #pragma unroll
        for (int o = 4; o > 0; o >>= 1) t += __shfl_xor_sync(~0u, t, o);
        if (lid == 0) sred[0] = t;
    }
    __syncthreads();
    const float inv = 1.0f / sred[0];
    v.x *= inv; v.y *= inv; v.z *= inv; v.w *= inv;
    ((float4*)row)[tid] = v;
}

// ---------------------------------------------------------------------------
extern "C" void kernel_launch(void* const* d_in, const int* in_sizes, int n_in,
                              void* d_out, int out_size)
{
    const float* x   = (const float*)d_in[0];
    const float* gns = (const float*)d_in[1];
    const float* gnb = (const float*)d_in[2];
    const float* wq  = (const float*)d_in[3];
    const float* bq  = (const float*)d_in[4];
    const float* wk  = (const float*)d_in[5];
    const float* bk  = (const float*)d_in[6];
    const float* wv  = (const float*)d_in[7];
    const float* bv  = (const float*)d_in[8];
    const float* wp  = (const float*)d_in[9];
    const float* bp  = (const float*)d_in[10];
    float* out = (float*)d_out;

    float *xn, *q, *k, *v, *attn, *o;
    cudaGetSymbolAddress((void**)&xn,   g_xn);
    cudaGetSymbolAddress((void**)&q,    g_q);
    cudaGetSymbolAddress((void**)&k,    g_k);
    cudaGetSymbolAddress((void**)&v,    g_v);
    cudaGetSymbolAddress((void**)&attn, g_attn);
    cudaGetSymbolAddress((void**)&o,    g_o);

    const long SX = (long)CC * NN;
    const long SA = (long)NN * NN;
    const float inv_sqrt_c = 1.0f / sqrtf((float)CC);
    const long EW_GRID = (long)BB * CC * NN / 4 / 256;

    constexpr int SM_QKV = SmemCfg<false, false, true >::BYTES;
    constexpr int SM_QK  = SmemCfg<true,  false, false>::BYTES;
    constexpr int SM_AV  = SmemCfg<false, true,  false>::BYTES;
    constexpr int SM_PR  = SmemCfg<false, false, false>::BYTES;
    cudaFuncSetAttribute(gemm_tc<false, false, true >,
                         cudaFuncAttributeMaxDynamicSharedMemorySize, SM_QKV);
    cudaFuncSetAttribute(gemm_tc<true,  false, false>,
                         cudaFuncAttributeMaxDynamicSharedMemorySize, SM_QK);
    cudaFuncSetAttribute(gemm_tc<false, true,  false>,
                         cudaFuncAttributeMaxDynamicSharedMemorySize, SM_AV);
    cudaFuncSetAttribute(gemm_tc<false, false, false>,
                         cudaFuncAttributeMaxDynamicSharedMemorySize, SM_PR);

    // 1. GroupNorm
    gn_kernel<<<BB * NG, 256>>>(x, gns, gnb, xn);

    // 2. q, k, v = W @ xn — single fused launch (z = 3*BB), then fused bias
    {
        dim3 grid(NN / TILE_N, CC / TILE_M, 3 * BB);
        gemm_tc<false, false, true><<<grid, 256, SM_QKV>>>(
            wq, wk, wv, 0, xn, SX, q, k, v, SX, CC, CC, NN, NN, 1.0f);
        bias3_kernel<<<EW_GRID, 256>>>(q, k, v, bq, bk, bv);
    }

    // 3. attn[i,j] = (1/sqrt(C)) * sum_c q[c,i] k[c,j]   (TA)
    {
        dim3 grid(NN / TILE_N, NN / TILE_M, BB);
        gemm_tc<true, false, false><<<grid, 256, SM_QK>>>(
            q, nullptr, nullptr, SX, k, SX, attn, nullptr, nullptr, SA,
            CC, NN, NN, NN, inv_sqrt_c);
    }

    // 4. softmax rows
    softmax_kernel<<<BB * NN, 256>>>(attn);

    // 5. o[c,i] = sum_j v[c,j] * A[i,j]   (TB)
    {
        dim3 grid(NN / TILE_N, CC / TILE_M, BB);
        gemm_tc<false, true, false><<<grid, 256, SM_AV>>>(
            v, nullptr, nullptr, SX, attn, SA, o, nullptr, nullptr, SX,
            NN, NN, NN, NN, 1.0f);
    }

    // 6. out = wp @ o, then out += bp + x
    {
        dim3 grid(NN / TILE_N, CC / TILE_M, BB);
        gemm_tc<false, false, false><<<grid, 256, SM_PR>>>(
            wp, nullptr, nullptr, 0, o, SX, out, nullptr, nullptr, SX,
            CC, CC, NN, NN, 1.0f);
        final_epi_kernel<<<EW_GRID, 256>>>(out, x, bp);
    }
}

// round 11
// speedup vs baseline: 2.3572x; 1.0704x over previous
#include <cuda_runtime.h>
#include <mma.h>
#include <math.h>
#include <type_traits>

using namespace nvcuda;

// Problem constants
#define BB   16
#define CC   512
#define NN   1024
#define NG   32
#define CPG  16
#define GSZ  (CPG*NN)

#define TILE_M 64
#define TILE_N 128
#define TILE_K 32
#define PAD    4

// Scratch (static device globals; no runtime allocation allowed)
__device__ float g_xn  [BB*CC*NN];   // group-normed x, [b][c][n]
__device__ float g_t   [BB*CC*NN];   // t = M1 xn + Wq^T bk
__device__ float g_attn[BB*NN*NN];   // S / probs
__device__ float g_z   [BB*CC*NN];   // z = xn A^T
__device__ float g_M1  [CC*CC];      // Wq^T Wk
__device__ float g_M2  [CC*CC];      // Wp Wv
__device__ float g_rvec[BB*NN];      // per-(b,j) bias for S
__device__ float g_vecs[3*CC + 32];  // tb | wt | cb | bqbk

// ---------------------------------------------------------------------------
__device__ __forceinline__ void cp_async16(void* smem, const void* gmem) {
    unsigned s = (unsigned)__cvta_generic_to_shared(smem);
    asm volatile("cp.async.cg.shared.global [%0], [%1], 16;\n" :: "r"(s), "l"(gmem));
}
__device__ __forceinline__ void cp_commit() {
    asm volatile("cp.async.commit_group;\n");
}
template<int N>
__device__ __forceinline__ void cp_wait() {
    asm volatile("cp.async.wait_group %0;\n" :: "n"(N));
}

// ---------------------------------------------------------------------------
// GroupNorm
// ---------------------------------------------------------------------------
__global__ __launch_bounds__(256) void gn_kernel(
    const float* __restrict__ x,
    const float* __restrict__ sc,
    const float* __restrict__ bi,
    float* __restrict__ out)
{
    const int bg = blockIdx.x;
    const float* xp = x   + (long)bg * GSZ;
    float*       op = out + (long)bg * GSZ;

    float s = 0.f, s2 = 0.f;
    for (int i = threadIdx.x; i < GSZ / 4; i += 256) {
        float4 v = ((const float4*)xp)[i];
        s  += v.x + v.y + v.z + v.w;
        s2 += v.x*v.x + v.y*v.y + v.z*v.z + v.w*v.w;
    }
    #pragma unroll
    for (int o = 16; o > 0; o >>= 1) {
        s  += __shfl_xor_sync(~0u, s,  o);
        s2 += __shfl_xor_sync(~0u, s2, o);
    }
    __shared__ float rs[8], rs2[8];
    const int wid = threadIdx.x >> 5, lid = threadIdx.x & 31;
    if (lid == 0) { rs[wid] = s; rs2[wid] = s2; }
    __syncthreads();
    if (threadIdx.x == 0) {
        float ts = 0.f, ts2 = 0.f;
        #pragma unroll
        for (int w = 0; w < 8; w++) { ts += rs[w]; ts2 += rs2[w]; }
        rs[0] = ts; rs2[0] = ts2;
    }
    __syncthreads();
    const float inv_n = 1.0f / (float)GSZ;
    const float mean  = rs[0] * inv_n;
    const float var   = rs2[0] * inv_n - mean * mean;
    const float rstd  = rsqrtf(var + 1e-5f);

    const int g = bg % NG;
    for (int i = threadIdx.x; i < GSZ / 4; i += 256) {
        const int c = g * CPG + (i >> 8);
        const float a = rstd * sc[c];
        const float b = bi[c] - mean * a;
        float4 v = ((const float4*)xp)[i];
        v.x = v.x * a + b; v.y = v.y * a + b;
        v.z = v.z * a + b; v.w = v.w * a + b;
        ((float4*)op)[i] = v;
    }
}

// ---------------------------------------------------------------------------
// Zero M1/M2 (must be re-zeroed every launch: split-K accumulates atomically)
// ---------------------------------------------------------------------------
__global__ __launch_bounds__(256) void zero_mm(float* __restrict__ m1,
                                               float* __restrict__ m2)
{
    const int i = blockIdx.x * 256 + threadIdx.x;   // 65536 float4 each
    const float4 z = {0.f, 0.f, 0.f, 0.f};
    ((float4*)m1)[i] = z;
    ((float4*)m2)[i] = z;
}

// ---------------------------------------------------------------------------
// Small bias-derived vectors:
//  tb[c]  = sum_d Wq[d][c] bk[d]           (row bias of t)
//  wt[c]  = sum_d Wk[d][c] bq[d]           (rvec weight)
//  cb[c]  = sum_d Wp[c][d] bv[d] + bp[c]   (row bias of out)
//  bqbk   = bq . bk
// ---------------------------------------------------------------------------
__global__ __launch_bounds__(512) void vecs_kernel(
    const float* __restrict__ wq, const float* __restrict__ wk,
    const float* __restrict__ wp,
    const float* __restrict__ bq, const float* __restrict__ bk,
    const float* __restrict__ bv, const float* __restrict__ bp,
    float* __restrict__ vecs)
{
    const int t = threadIdx.x;
    if (blockIdx.x == 0) {
        float s = 0.f;
        for (int d = 0; d < CC; d++) s += wq[d*CC + t] * bk[d];
        vecs[t] = s;
    } else if (blockIdx.x == 1) {
        float s = 0.f;
        for (int d = 0; d < CC; d++) s += wk[d*CC + t] * bq[d];
        vecs[CC + t] = s;
    } else if (blockIdx.x == 2) {
        float s = 0.f;
        for (int d = 0; d < CC; d++) s += wp[t*CC + d] * bv[d];
        vecs[2*CC + t] = s + bp[t];
    } else {
        __shared__ float red[16];
        float s = bq[t] * bk[t];
        #pragma unroll
        for (int o = 16; o > 0; o >>= 1) s += __shfl_xor_sync(~0u, s, o);
        if ((t & 31) == 0) red[t >> 5] = s;
        __syncthreads();
        if (t == 0) {
            float ts = 0.f;
            #pragma unroll
            for (int w = 0; w < 16; w++) ts += red[w];
            vecs[3*CC] = ts;
        }
    }
}

// ---------------------------------------------------------------------------
// rvec[b][j] = wt . xn[b][:,j] + bqbk
// ---------------------------------------------------------------------------
__global__ __launch_bounds__(256) void rvec_kernel(
    const float* __restrict__ xn, const float* __restrict__ vecs,
    float* __restrict__ rvec)
{
    __shared__ float wt[CC];
    const int b = blockIdx.y;
    const int j = blockIdx.x * 256 + threadIdx.x;
    for (int i = threadIdx.x; i < CC; i += 256) wt[i] = vecs[CC + i];
    __syncthreads();
    const float* xb = xn + (long)b * CC * NN + j;
    float s = 0.f;
    #pragma unroll 8
    for (int c = 0; c < CC; c++) s += wt[c] * xb[(long)c * NN];
    rvec[b * NN + j] = s + vecs[3*CC];
}

// ---------------------------------------------------------------------------
// TF32 tensor-core GEMM. 64x128 block tile, 8 warps of 32x32, 2-stage
// cp.async ring, 3 CTAs/SM, smem-staged epilogue.
//   C = op(A) * op(B) with epilogue, batched over blockIdx.z (except EPI 4).
//   TA: A(m,k) = A[k*lda + m]   TB: B(k,n) = B[n*ldb + k]
// EPI: 0: C = alpha*acc
//      1: C = alpha*(acc + bias[b][n])      (bias batch-strided by sBias)
//      2: C = acc + bias[m]
//      3: C = acc + bias[m] + resid[b][m,n]
//      4: atomicAdd(C, acc); blockIdx.z = K-split slice (koff = z*K), b=0
// ---------------------------------------------------------------------------
template<bool TA, bool TB>
struct SmemCfg {
    static constexpr int A_LD   = TA ? (TILE_M + PAD) : (TILE_K + PAD);
    static constexpr int A_SIZE = TA ? TILE_K * A_LD  : TILE_M * A_LD;
    static constexpr int B_LD   = TB ? (TILE_K + PAD) : (TILE_N + PAD);
    static constexpr int B_SIZE = TB ? TILE_N * B_LD  : TILE_K * B_LD;
    static constexpr int PIPE   = (2 * A_SIZE + 2 * B_SIZE) * 4;
    static constexpr int BYTES  = PIPE > TILE_M*TILE_N*4 ? PIPE : TILE_M*TILE_N*4;
};

template<bool TA, bool TB, int EPI>
__global__ __launch_bounds__(256, 3) void gemm_tc(
    const float* __restrict__ Ag, long sA,
    const float* __restrict__ Bg, long sB,
    float*       __restrict__ Cg, long sC,
    const float* __restrict__ bias, long sBias,
    const float* __restrict__ resid, long sR,
    int K, int lda, int ldb, int ldc, float alpha)
{
    using Cfg = SmemCfg<TA, TB>;
    constexpr int A_LD = Cfg::A_LD, A_SIZE = Cfg::A_SIZE;
    constexpr int B_LD = Cfg::B_LD, B_SIZE = Cfg::B_SIZE;

    extern __shared__ float smem[];
    float* AsBase = smem;
    float* BsBase = smem + 2 * A_SIZE;

    const int zz = blockIdx.z;
    const int b  = (EPI == 4) ? 0 : zz;
    const int koff = (EPI == 4) ? zz * K : 0;
    const float* A = Ag + b * sA;
    const float* B = Bg + b * sB;
    float*       C = Cg + b * sC;

    const int m0 = blockIdx.y * TILE_M;
    const int n0 = blockIdx.x * TILE_N;
    const int tid = threadIdx.x;
    const int wid = tid >> 5;
    const int wm = wid >> 2;    // 2 warp rows (32 m each)
    const int wn = wid & 3;     // 4 warp cols (32 n each)

    typedef typename std::conditional<TA, wmma::col_major, wmma::row_major>::type ALay;
    typedef typename std::conditional<TB, wmma::col_major, wmma::row_major>::type BLay;

    wmma::fragment<wmma::accumulator, 16, 16, 8, float> acc[2][2];
    #pragma unroll
    for (int i = 0; i < 2; i++)
        #pragma unroll
        for (int j = 0; j < 2; j++)
            wmma::fill_fragment(acc[i][j], 0.0f);

    auto load_tiles = [&](int s, int k0) {
        float* as = AsBase + s * A_SIZE;
        float* bs = BsBase + s * B_SIZE;
        const int kg = koff + k0;
        if (!TA) {
            #pragma unroll
            for (int p = 0; p < 2; p++) {
                const int c = tid + p * 256;
                const int m = c >> 3, kc = c & 7;
                cp_async16(&as[m * A_LD + kc * 4],
                           A + (long)(m0 + m) * lda + kg + kc * 4);
            }
        } else {
            #pragma unroll
            for (int p = 0; p < 2; p++) {
                const int c = tid + p * 256;
                const int kk = c >> 4, mc = c & 15;
                cp_async16(&as[kk * A_LD + mc * 4],
                           A + (long)(kg + kk) * lda + m0 + mc * 4);
            }
        }
        if (!TB) {
            #pragma unroll
            for (int p = 0; p < 4; p++) {
                const int c = tid + p * 256;
                const int kk = c >> 5, nc = c & 31;
                cp_async16(&bs[kk * B_LD + nc * 4],
                           B + (long)(kg + kk) * ldb + n0 + nc * 4);
            }
        } else {
            #pragma unroll
            for (int p = 0; p < 4; p++) {
                const int c = tid + p * 256;
                const int n = c >> 3, kc = c & 7;
                cp_async16(&bs[n * B_LD + kc * 4],
                           B + (long)(n0 + n) * ldb + kg + kc * 4);
            }
        }
    };

    const int KT = K / TILE_K;
    load_tiles(0, 0);
    cp_commit();

    for (int kt = 0; kt < KT; kt++) {
        const int s = kt & 1;
        cp_wait<0>();
        __syncthreads();

        if (kt + 1 < KT) {
            load_tiles(s ^ 1, (kt + 1) * TILE_K);
            cp_commit();
        }

        const float* as = AsBase + s * A_SIZE;
        const float* bs = BsBase + s * B_SIZE;
        #pragma unroll
        for (int kf = 0; kf < TILE_K / 8; kf++) {
            wmma::fragment<wmma::matrix_a, 16, 16, 8, wmma::precision::tf32, ALay> af[2];
            wmma::fragment<wmma::matrix_b, 16, 16, 8, wmma::precision::tf32, BLay> bf[2];
            #pragma unroll
            for (int i = 0; i < 2; i++) {
                const float* p = TA ? &as[(kf*8) * A_LD + wm*32 + i*16]
                                    : &as[(wm*32 + i*16) * A_LD + kf*8];
                wmma::load_matrix_sync(af[i], p, A_LD);
            }
            #pragma unroll
            for (int j = 0; j < 2; j++) {
                const float* p = TB ? &bs[(wn*32 + j*16) * B_LD + kf*8]
                                    : &bs[(kf*8) * B_LD + wn*32 + j*16];
                wmma::load_matrix_sync(bf[j], p, B_LD);
            }
            #pragma unroll
            for (int i = 0; i < 2; i++)
                #pragma unroll
                for (int j = 0; j < 2; j++)
                    wmma::mma_sync(acc[i][j], af[i], bf[j], acc[i][j]);
        }
    }

    // ---- epilogue: stage C tile in smem, then elementwise ----
    __syncthreads();
    float* cs = smem;
    #pragma unroll
    for (int i = 0; i < 2; i++)
        #pragma unroll
        for (int j = 0; j < 2; j++)
            wmma::store_matrix_sync(&cs[(wm*32 + i*16) * TILE_N + wn*32 + j*16],
                                    acc[i][j], TILE_N, wmma::mem_row_major);
    __syncthreads();

    if (EPI == 4) {
        for (int idx = tid; idx < TILE_M * TILE_N; idx += 256) {
            const int m = idx >> 7, n = idx & 127;
            atomicAdd(&C[(long)(m0 + m) * ldc + n0 + n], cs[idx]);
        }
    } else {
        const float* bb = (EPI == 1) ? bias + zz * sBias : bias;
        #pragma unroll
        for (int p = 0; p < TILE_M * TILE_N / 4 / 256; p++) {
            const int idx = tid + p * 256;
            const int m = idx >> 5, nc = (idx & 31) * 4;
            float4 v = *(float4*)&cs[m * TILE_N + nc];
            if (EPI == 0) {
                v.x *= alpha; v.y *= alpha; v.z *= alpha; v.w *= alpha;
            } else if (EPI == 1) {
                const int n = n0 + nc;
                v.x = (v.x + bb[n+0]) * alpha;
                v.y = (v.y + bb[n+1]) * alpha;
                v.z = (v.z + bb[n+2]) * alpha;
                v.w = (v.w + bb[n+3]) * alpha;
            } else {
                const float rb = bias[m0 + m];
                v.x += rb; v.y += rb; v.z += rb; v.w += rb;
                if (EPI == 3) {
                    float4 r = *(const float4*)&resid[zz * sR + (long)(m0+m) * ldc + n0 + nc];
                    v.x += r.x; v.y += r.y; v.z += r.z; v.w += r.w;
                }
            }
            *(float4*)&C[(long)(m0 + m) * ldc + n0 + nc] = v;
        }
    }
}

// ---------------------------------------------------------------------------
__global__ __launch_bounds__(256) void softmax_kernel(float* __restrict__ attn)
{
    float* row = attn + (long)blockIdx.x * NN;
    const int tid = threadIdx.x;
    const int wid = tid >> 5, lid = tid & 31;
    __shared__ float sred[8];

    float4 v = ((float4*)row)[tid];
    float mx = fmaxf(fmaxf(v.x, v.y), fmaxf(v.z, v.w));
    #pragma unroll
    for (int o = 16; o > 0; o >>= 1) mx = fmaxf(mx, __shfl_xor_sync(~0u, mx, o));
    if (lid == 0) sred[wid] = mx;
    __syncthreads();
    if (wid == 0) {
        float m2 = (lid < 8) ? sred[lid] : -1e30f;
        #pragma unroll
        for (int o = 4; o > 0; o >>= 1) m2 = fmaxf(m2, __shfl_xor_sync(~0u, m2, o));
        if (lid == 0) sred[0] = m2;
    }
    __syncthreads();
    mx = sred[0];

    v.x = __expf(v.x - mx); v.y = __expf(v.y - mx);
    v.z = __expf(v.z - mx); v.w = __expf(v.w - mx);
    float s = v.x + v.y + v.z + v.w;
    #pragma unroll
    for (int o = 16; o > 0; o >>= 1) s += __shfl_xor_sync(~0u, s, o);
    __syncthreads();
    if (lid == 0) sred[wid] = s;
    __syncthreads();
    if (wid == 0) {
        float t = (lid < 8) ? sred[lid] : 0.f;
        #pragma unroll
        for (int o = 4; o > 0; o >>= 1) t += __shfl_xor_sync(~0u, t, o);
        if (lid == 0) sred[0] = t;
    }
    __syncthreads();
    const float inv = 1.0f / sred[0];
    v.x *= inv; v.y *= inv; v.z *= inv; v.w *= inv;
    ((float4*)row)[tid] = v;
}

// ---------------------------------------------------------------------------
extern "C" void kernel_launch(void* const* d_in, const int* in_sizes, int n_in,
                              void* d_out, int out_size)
{
    const float* x   = (const float*)d_in[0];
    const float* gns = (const float*)d_in[1];
    const float* gnb = (const float*)d_in[2];
    const float* wq  = (const float*)d_in[3];
    const float* bq  = (const float*)d_in[4];
    const float* wk  = (const float*)d_in[5];
    const float* bk  = (const float*)d_in[6];
    const float* wv  = (const float*)d_in[7];
    const float* bv  = (const float*)d_in[8];
    const float* wp  = (const float*)d_in[9];
    const float* bp  = (const float*)d_in[10];
    float* out = (float*)d_out;

    float *xn, *t, *attn, *z, *m1, *m2, *rvec, *vecs;
    cudaGetSymbolAddress((void**)&xn,   g_xn);
    cudaGetSymbolAddress((void**)&t,    g_t);
    cudaGetSymbolAddress((void**)&attn, g_attn);
    cudaGetSymbolAddress((void**)&z,    g_z);
    cudaGetSymbolAddress((void**)&m1,   g_M1);
    cudaGetSymbolAddress((void**)&m2,   g_M2);
    cudaGetSymbolAddress((void**)&rvec, g_rvec);
    cudaGetSymbolAddress((void**)&vecs, g_vecs);

    const long SX = (long)CC * NN;
    const long SA = (long)NN * NN;
    const float isc = 1.0f / sqrtf((float)CC);

    constexpr int SM_TF = SmemCfg<true,  false>::BYTES;
    constexpr int SM_FF = SmemCfg<false, false>::BYTES;
    constexpr int SM_FT = SmemCfg<false, true >::BYTES;
    cudaFuncSetAttribute(gemm_tc<true,  false, 4>, cudaFuncAttributeMaxDynamicSharedMemorySize, SM_TF);
    cudaFuncSetAttribute(gemm_tc<false, false, 4>, cudaFuncAttributeMaxDynamicSharedMemorySize, SM_FF);
    cudaFuncSetAttribute(gemm_tc<false, false, 2>, cudaFuncAttributeMaxDynamicSharedMemorySize, SM_FF);
    cudaFuncSetAttribute(gemm_tc<true,  false, 1>, cudaFuncAttributeMaxDynamicSharedMemorySize, SM_TF);
    cudaFuncSetAttribute(gemm_tc<false, true,  0>, cudaFuncAttributeMaxDynamicSharedMemorySize, SM_FT);
    cudaFuncSetAttribute(gemm_tc<false, false, 3>, cudaFuncAttributeMaxDynamicSharedMemorySize, SM_FF);

    // 0. zero split-K accumulators (must happen every replay)
    zero_mm<<<256, 256>>>(m1, m2);

    // 1. GroupNorm -> xn
    gn_kernel<<<BB * NG, 256>>>(x, gns, gnb, xn);

    // 2. bias-derived vectors (weights/biases only)
    vecs_kernel<<<4, 512>>>(wq, wk, wp, bq, bk, bv, bp, vecs);

    // 3. M1 = Wq^T Wk, M2 = Wp Wv  (split-K=8, atomic accumulate)
    gemm_tc<true,  false, 4><<<dim3(4, 8, 8), 256, SM_TF>>>(
        wq, 0, wk, 0, m1, 0, nullptr, 0, nullptr, 0, 64, CC, CC, CC, 1.0f);
    gemm_tc<false, false, 4><<<dim3(4, 8, 8), 256, SM_FF>>>(
        wp, 0, wv, 0, m2, 0, nullptr, 0, nullptr, 0, 64, CC, CC, CC, 1.0f);

    // 4. t = M1 xn + tb[row]            M=512, N=1024, K=512
    gemm_tc<false, false, 2><<<dim3(8, 8, BB), 256, SM_FF>>>(
        m1, 0, xn, SX, t, SX, vecs, 0, nullptr, 0, CC, CC, NN, NN, 1.0f);

    // 5. rvec[b][j] = wt . xn[b][:,j] + bqbk
    rvec_kernel<<<dim3(NN/256, BB), 256>>>(xn, vecs, rvec);

    // 6. S = (xn^T t + rvec[col]) / sqrt(C)    M=N=1024, K=512
    gemm_tc<true, false, 1><<<dim3(8, 16, BB), 256, SM_TF>>>(
        xn, SX, t, SX, attn, SA, rvec, NN, nullptr, 0, CC, NN, NN, NN, isc);

    // 7. softmax rows
    softmax_kernel<<<BB * NN, 256>>>(attn);

    // 8. z = xn A^T                     M=512, N=1024, K=1024
    gemm_tc<false, true, 0><<<dim3(8, 8, BB), 256, SM_FT>>>(
        xn, SX, attn, SA, z, SX, nullptr, 0, nullptr, 0, NN, NN, NN, NN, 1.0f);

    // 9. out = M2 z + cb[row] + x       M=512, N=1024, K=512
    gemm_tc<false, false, 3><<<dim3(8, 8, BB), 256, SM_FF>>>(
        m2, 0, z, SX, out, SX, vecs + 2*CC, 0, x, SX, CC, CC, NN, NN, 1.0f);
}

// round 12
// speedup vs baseline: 5.5287x; 2.3454x over previous
#include <cuda_runtime.h>
#include <cuda_fp16.h>
#include <mma.h>
#include <math.h>
#include <type_traits>

using namespace nvcuda;

// Problem constants
#define BB   16
#define CC   512
#define NN   1024
#define NG   32
#define CPG  16
#define GSZ  (CPG*NN)

#define TILE_M 64
#define TILE_N 128
#define TILE_K 64      // halves per K-chunk
#define HPAD   8       // pad halves (16B)

// Scratch (static device globals)
__device__ __half g_xnh[BB*CC*NN];   // group-normed x, fp16 [b][c][n]
__device__ __half g_th [BB*CC*NN];   // t = M1 xn + tb
__device__ float  g_S  [BB*NN*NN];   // logits (fp32)
__device__ __half g_Ph [BB*NN*NN];   // softmax probs (fp16)
__device__ __half g_zh [BB*CC*NN];   // z = xn A^T
__device__ float  g_M1f[CC*CC];      // split-K accumulators
__device__ float  g_M2f[CC*CC];
__device__ __half g_M1h[CC*CC];
__device__ __half g_M2h[CC*CC];
__device__ __half g_wh [4*CC*CC];    // fp16 weights: wq|wk|wv|wp
__device__ float  g_rvec[BB*NN];
__device__ float  g_vecs[3*CC + 32]; // tb | wt | cb | bqbk

// ---------------------------------------------------------------------------
__device__ __forceinline__ void cp_async16(void* smem, const void* gmem) {
    unsigned s = (unsigned)__cvta_generic_to_shared(smem);
    asm volatile("cp.async.cg.shared.global [%0], [%1], 16;\n" :: "r"(s), "l"(gmem));
}
__device__ __forceinline__ void cp_commit() {
    asm volatile("cp.async.commit_group;\n");
}
template<int N>
__device__ __forceinline__ void cp_wait() {
    asm volatile("cp.async.wait_group %0;\n" :: "n"(N));
}

// ---------------------------------------------------------------------------
// GroupNorm -> fp16 xn
// ---------------------------------------------------------------------------
__global__ __launch_bounds__(256) void gn_kernel(
    const float* __restrict__ x,
    const float* __restrict__ sc,
    const float* __restrict__ bi,
    __half* __restrict__ out)
{
    const int bg = blockIdx.x;
    const float* xp = x + (long)bg * GSZ;
    __half*      op = out + (long)bg * GSZ;

    float s = 0.f, s2 = 0.f;
    for (int i = threadIdx.x; i < GSZ / 4; i += 256) {
        float4 v = ((const float4*)xp)[i];
        s  += v.x + v.y + v.z + v.w;
        s2 += v.x*v.x + v.y*v.y + v.z*v.z + v.w*v.w;
    }
    #pragma unroll
    for (int o = 16; o > 0; o >>= 1) {
        s  += __shfl_xor_sync(~0u, s,  o);
        s2 += __shfl_xor_sync(~0u, s2, o);
    }
    __shared__ float rs[8], rs2[8];
    const int wid = threadIdx.x >> 5, lid = threadIdx.x & 31;
    if (lid == 0) { rs[wid] = s; rs2[wid] = s2; }
    __syncthreads();
    if (threadIdx.x == 0) {
        float ts = 0.f, ts2 = 0.f;
        #pragma unroll
        for (int w = 0; w < 8; w++) { ts += rs[w]; ts2 += rs2[w]; }
        rs[0] = ts; rs2[0] = ts2;
    }
    __syncthreads();
    const float inv_n = 1.0f / (float)GSZ;
    const float mean  = rs[0] * inv_n;
    const float var   = rs2[0] * inv_n - mean * mean;
    const float rstd  = rsqrtf(var + 1e-5f);

    const int g = bg % NG;
    for (int i = threadIdx.x; i < GSZ / 4; i += 256) {
        const int c = g * CPG + (i >> 8);
        const float a = rstd * sc[c];
        const float b = bi[c] - mean * a;
        float4 v = ((const float4*)xp)[i];
        ((__half2*)op)[2*i]   = __floats2half2_rn(v.x * a + b, v.y * a + b);
        ((__half2*)op)[2*i+1] = __floats2half2_rn(v.z * a + b, v.w * a + b);
    }
}

// ---------------------------------------------------------------------------
// fp32 -> fp16 conversion (n/4 float4 per grid)
// ---------------------------------------------------------------------------
__global__ __launch_bounds__(256) void conv_h(
    const float* __restrict__ s, __half* __restrict__ d)
{
    const int i = blockIdx.x * 256 + threadIdx.x;
    float4 v = ((const float4*)s)[i];
    ((__half2*)d)[2*i]   = __floats2half2_rn(v.x, v.y);
    ((__half2*)d)[2*i+1] = __floats2half2_rn(v.z, v.w);
}

__global__ __launch_bounds__(256) void zero_mm(float* __restrict__ m1,
                                               float* __restrict__ m2)
{
    const int i = blockIdx.x * 256 + threadIdx.x;
    const float4 z = {0.f, 0.f, 0.f, 0.f};
    ((float4*)m1)[i] = z;
    ((float4*)m2)[i] = z;
}

// ---------------------------------------------------------------------------
// Bias-derived vectors (fp32 weights)
// ---------------------------------------------------------------------------
__global__ __launch_bounds__(512) void vecs_kernel(
    const float* __restrict__ wq, const float* __restrict__ wk,
    const float* __restrict__ wp,
    const float* __restrict__ bq, const float* __restrict__ bk,
    const float* __restrict__ bv, const float* __restrict__ bp,
    float* __restrict__ vecs)
{
    const int t = threadIdx.x;
    if (blockIdx.x == 0) {
        float s = 0.f;
        for (int d = 0; d < CC; d++) s += wq[d*CC + t] * bk[d];
        vecs[t] = s;
    } else if (blockIdx.x == 1) {
        float s = 0.f;
        for (int d = 0; d < CC; d++) s += wk[d*CC + t] * bq[d];
        vecs[CC + t] = s;
    } else if (blockIdx.x == 2) {
        float s = 0.f;
        for (int d = 0; d < CC; d++) s += wp[t*CC + d] * bv[d];
        vecs[2*CC + t] = s + bp[t];
    } else {
        __shared__ float red[16];
        float s = bq[t] * bk[t];
        #pragma unroll
        for (int o = 16; o > 0; o >>= 1) s += __shfl_xor_sync(~0u, s, o);
        if ((t & 31) == 0) red[t >> 5] = s;
        __syncthreads();
        if (t == 0) {
            float ts = 0.f;
            #pragma unroll
            for (int w = 0; w < 16; w++) ts += red[w];
            vecs[3*CC] = ts;
        }
    }
}

// ---------------------------------------------------------------------------
// rvec[b][j] = wt . xn[b][:,j] + bqbk   (xn in fp16)
// ---------------------------------------------------------------------------
__global__ __launch_bounds__(256) void rvec_kernel(
    const __half* __restrict__ xn, const float* __restrict__ vecs,
    float* __restrict__ rvec)
{
    __shared__ float wt[CC];
    const int b = blockIdx.y;
    const int j = blockIdx.x * 256 + threadIdx.x;
    for (int i = threadIdx.x; i < CC; i += 256) wt[i] = vecs[CC + i];
    __syncthreads();
    const __half* xb = xn + (long)b * CC * NN + j;
    float s = 0.f;
    #pragma unroll 8
    for (int c = 0; c < CC; c++) s += wt[c] * __half2float(xb[(long)c * NN]);
    rvec[b * NN + j] = s + vecs[3*CC];
}

// ---------------------------------------------------------------------------
// FP16 tensor-core GEMM (fp32 accumulate). 64x128 block tile, 8 warps of
// 32x32 (m16n16k16 x 2x2), TILE_K=64, 2-stage cp.async, 3 CTAs/SM.
//   TA: A(m,k) = A[k*lda + m]   TB: B(k,n) = B[n*ldb + k]
// EPI: 0: C = alpha*acc                   (OUTH)
//      1: C = alpha*(acc + bias[b][n])    (fp32 out)
//      2: C = acc + bias[m]               (OUTH)
//      3: C = acc + bias[m] + resid       (fp32 out)
//      4: atomicAdd(fp32 C); z = K-slice
// ---------------------------------------------------------------------------
template<bool TA, bool TB>
struct SmemCfg {
    static constexpr int A_LD   = TA ? (TILE_M + HPAD) : (TILE_K + HPAD);   // 72
    static constexpr int A_SIZE = TA ? TILE_K * A_LD   : TILE_M * A_LD;     // 4608
    static constexpr int B_LD   = TB ? (TILE_K + HPAD) : (TILE_N + HPAD);
    static constexpr int B_SIZE = TB ? TILE_N * B_LD   : TILE_K * B_LD;
    static constexpr int PIPE   = (2 * A_SIZE + 2 * B_SIZE) * 2;
    static constexpr int EPIB   = TILE_M * TILE_N * 4;
    static constexpr int BYTES  = PIPE > EPIB ? PIPE : EPIB;
};

template<bool TA, bool TB, int EPI, bool OUTH>
__global__ __launch_bounds__(256, 3) void gemm_h(
    const __half* __restrict__ Ag, long sA,
    const __half* __restrict__ Bg, long sB,
    void*         __restrict__ Cg, long sC,
    const float* __restrict__ bias, long sBias,
    const float* __restrict__ resid, long sR,
    int K, int lda, int ldb, int ldc, float alpha)
{
    using Cfg = SmemCfg<TA, TB>;
    constexpr int A_LD = Cfg::A_LD, A_SIZE = Cfg::A_SIZE;
    constexpr int B_LD = Cfg::B_LD, B_SIZE = Cfg::B_SIZE;

    extern __shared__ __half smem[];
    __half* AsBase = smem;
    __half* BsBase = smem + 2 * A_SIZE;

    const int zz = blockIdx.z;
    const int b  = (EPI == 4) ? 0 : zz;
    const int koff = (EPI == 4) ? zz * K : 0;
    const __half* A = Ag + b * sA;
    const __half* B = Bg + b * sB;

    const int m0 = blockIdx.y * TILE_M;
    const int n0 = blockIdx.x * TILE_N;
    const int tid = threadIdx.x;
    const int wid = tid >> 5;
    const int wm = wid >> 2;    // 2 warp rows (32 m)
    const int wn = wid & 3;     // 4 warp cols (32 n)

    typedef typename std::conditional<TA, wmma::col_major, wmma::row_major>::type ALay;
    typedef typename std::conditional<TB, wmma::col_major, wmma::row_major>::type BLay;

    wmma::fragment<wmma::accumulator, 16, 16, 16, float> acc[2][2];
    #pragma unroll
    for (int i = 0; i < 2; i++)
        #pragma unroll
        for (int j = 0; j < 2; j++)
            wmma::fill_fragment(acc[i][j], 0.0f);

    auto load_tiles = [&](int s, int k0) {
        __half* as = AsBase + s * A_SIZE;
        __half* bs = BsBase + s * B_SIZE;
        const int kg = koff + k0;
        // A tile: 64x64 halves = 512 chunks (2/thread)
        if (!TA) {
            #pragma unroll
            for (int p = 0; p < 2; p++) {
                const int c = tid + p * 256;
                const int m = c >> 3, kc = c & 7;
                cp_async16(&as[m * A_LD + kc * 8],
                           A + (long)(m0 + m) * lda + kg + kc * 8);
            }
        } else {
            #pragma unroll
            for (int p = 0; p < 2; p++) {
                const int c = tid + p * 256;
                const int kk = c >> 3, mc = c & 7;
                cp_async16(&as[kk * A_LD + mc * 8],
                           A + (long)(kg + kk) * lda + m0 + mc * 8);
            }
        }
        // B tile: 64x128 halves = 1024 chunks (4/thread)
        if (!TB) {
            #pragma unroll
            for (int p = 0; p < 4; p++) {
                const int c = tid + p * 256;
                const int kk = c >> 4, nc = c & 15;
                cp_async16(&bs[kk * B_LD + nc * 8],
                           B + (long)(kg + kk) * ldb + n0 + nc * 8);
            }
        } else {
            #pragma unroll
            for (int p = 0; p < 4; p++) {
                const int c = tid + p * 256;
                const int n = c >> 3, kc = c & 7;
                cp_async16(&bs[n * B_LD + kc * 8],
                           B + (long)(n0 + n) * ldb + kg + kc * 8);
            }
        }
    };

    const int KT = K / TILE_K;
    load_tiles(0, 0);
    cp_commit();

    for (int kt = 0; kt < KT; kt++) {
        const int s = kt & 1;
        cp_wait<0>();
        __syncthreads();

        if (kt + 1 < KT) {
            load_tiles(s ^ 1, (kt + 1) * TILE_K);
            cp_commit();
        }

        const __half* as = AsBase + s * A_SIZE;
        const __half* bs = BsBase + s * B_SIZE;
        #pragma unroll
        for (int kf = 0; kf < TILE_K / 16; kf++) {
            wmma::fragment<wmma::matrix_a, 16, 16, 16, __half, ALay> af[2];
            wmma::fragment<wmma::matrix_b, 16, 16, 16, __half, BLay> bf[2];
            #pragma unroll
            for (int i = 0; i < 2; i++) {
                const __half* p = TA ? &as[(kf*16) * A_LD + wm*32 + i*16]
                                     : &as[(wm*32 + i*16) * A_LD + kf*16];
                wmma::load_matrix_sync(af[i], p, A_LD);
            }
            #pragma unroll
            for (int j = 0; j < 2; j++) {
                const __half* p = TB ? &bs[(wn*32 + j*16) * B_LD + kf*16]
                                     : &bs[(kf*16) * B_LD + wn*32 + j*16];
                wmma::load_matrix_sync(bf[j], p, B_LD);
            }
            #pragma unroll
            for (int i = 0; i < 2; i++)
                #pragma unroll
                for (int j = 0; j < 2; j++)
                    wmma::mma_sync(acc[i][j], af[i], bf[j], acc[i][j]);
        }
    }

    // ---- epilogue: stage tile in smem (fp32), then elementwise ----
    __syncthreads();
    float* cs = (float*)smem;
    #pragma unroll
    for (int i = 0; i < 2; i++)
        #pragma unroll
        for (int j = 0; j < 2; j++)
            wmma::store_matrix_sync(&cs[(wm*32 + i*16) * TILE_N + wn*32 + j*16],
                                    acc[i][j], TILE_N, wmma::mem_row_major);
    __syncthreads();

    if (EPI == 4) {
        float* C = (float*)Cg;
        for (int idx = tid; idx < TILE_M * TILE_N; idx += 256) {
            const int m = idx >> 7, n = idx & 127;
            atomicAdd(&C[(long)(m0 + m) * ldc + n0 + n], cs[idx]);
        }
    } else {
        const float* bb = (EPI == 1) ? bias + zz * sBias : bias;
        #pragma unroll
        for (int p = 0; p < TILE_M * TILE_N / 4 / 256; p++) {
            const int idx = tid + p * 256;
            const int m = idx >> 5, nc = (idx & 31) * 4;
            float4 v = *(float4*)&cs[m * TILE_N + nc];
            if (EPI == 0) {
                v.x *= alpha; v.y *= alpha; v.z *= alpha; v.w *= alpha;
            } else if (EPI == 1) {
                const int n = n0 + nc;
                v.x = (v.x + bb[n+0]) * alpha;
                v.y = (v.y + bb[n+1]) * alpha;
                v.z = (v.z + bb[n+2]) * alpha;
                v.w = (v.w + bb[n+3]) * alpha;
            } else {
                const float rb = bias[m0 + m];
                v.x += rb; v.y += rb; v.z += rb; v.w += rb;
                if (EPI == 3) {
                    float4 r = *(const float4*)&resid[zz * sR + (long)(m0+m) * ldc + n0 + nc];
                    v.x += r.x; v.y += r.y; v.z += r.z; v.w += r.w;
                }
            }
            const long base = (long)b * sC + (long)(m0 + m) * ldc + n0 + nc;
            if (OUTH) {
                __half2* Ch = (__half2*)((__half*)Cg + base);
                Ch[0] = __floats2half2_rn(v.x, v.y);
                Ch[1] = __floats2half2_rn(v.z, v.w);
            } else {
                *(float4*)((float*)Cg + base) = v;
            }
        }
    }
}

// ---------------------------------------------------------------------------
// Row softmax: fp32 logits in, fp16 probs out
// ---------------------------------------------------------------------------
__global__ __launch_bounds__(256) void softmax_kernel(
    const float* __restrict__ S, __half* __restrict__ P)
{
    const float* row = S + (long)blockIdx.x * NN;
    __half*      po  = P + (long)blockIdx.x * NN;
    const int tid = threadIdx.x;
    const int wid = tid >> 5, lid = tid & 31;
    __shared__ float sred[8];

    float4 v = ((const float4*)row)[tid];
    float mx = fmaxf(fmaxf(v.x, v.y), fmaxf(v.z, v.w));
    #pragma unroll
    for (int o = 16; o > 0; o >>= 1) mx = fmaxf(mx, __shfl_xor_sync(~0u, mx, o));
    if (lid == 0) sred[wid] = mx;
    __syncthreads();
    if (wid == 0) {
        float m2 = (lid < 8) ? sred[lid] : -1e30f;
        #pragma unroll
        for (int o = 4; o > 0; o >>= 1) m2 = fmaxf(m2, __shfl_xor_sync(~0u, m2, o));
        if (lid == 0) sred[0] = m2;
    }
    __syncthreads();
    mx = sred[0];

    v.x = __expf(v.x - mx); v.y = __expf(v.y - mx);
    v.z = __expf(v.z - mx); v.w = __expf(v.w - mx);
    float s = v.x + v.y + v.z + v.w;
    #pragma unroll
    for (int o = 16; o > 0; o >>= 1) s += __shfl_xor_sync(~0u, s, o);
    __syncthreads();
    if (lid == 0) sred[wid] = s;
    __syncthreads();
    if (wid == 0) {
        float t = (lid < 8) ? sred[lid] : 0.f;
        #pragma unroll
        for (int o = 4; o > 0; o >>= 1) t += __shfl_xor_sync(~0u, t, o);
        if (lid == 0) sred[0] = t;
    }
    __syncthreads();
    const float inv = 1.0f / sred[0];
    ((__half2*)po)[2*tid]   = __floats2half2_rn(v.x * inv, v.y * inv);
    ((__half2*)po)[2*tid+1] = __floats2half2_rn(v.z * inv, v.w * inv);
}

// ---------------------------------------------------------------------------
extern "C" void kernel_launch(void* const* d_in, const int* in_sizes, int n_in,
                              void* d_out, int out_size)
{
    const float* x   = (const float*)d_in[0];
    const float* gns = (const float*)d_in[1];
    const float* gnb = (const float*)d_in[2];
    const float* wq  = (const float*)d_in[3];
    const float* bq  = (const float*)d_in[4];
    const float* wk  = (const float*)d_in[5];
    const float* bk  = (const float*)d_in[6];
    const float* wv  = (const float*)d_in[7];
    const float* bv  = (const float*)d_in[8];
    const float* wp  = (const float*)d_in[9];
    const float* bp  = (const float*)d_in[10];
    float* out = (float*)d_out;

    __half *xnh, *th, *Ph, *zh, *m1h, *m2h, *wh;
    float *S, *m1f, *m2f, *rvec, *vecs;
    cudaGetSymbolAddress((void**)&xnh,  g_xnh);
    cudaGetSymbolAddress((void**)&th,   g_th);
    cudaGetSymbolAddress((void**)&S,    g_S);
    cudaGetSymbolAddress((void**)&Ph,   g_Ph);
    cudaGetSymbolAddress((void**)&zh,   g_zh);
    cudaGetSymbolAddress((void**)&m1f,  g_M1f);
    cudaGetSymbolAddress((void**)&m2f,  g_M2f);
    cudaGetSymbolAddress((void**)&m1h,  g_M1h);
    cudaGetSymbolAddress((void**)&m2h,  g_M2h);
    cudaGetSymbolAddress((void**)&wh,   g_wh);
    cudaGetSymbolAddress((void**)&rvec, g_rvec);
    cudaGetSymbolAddress((void**)&vecs, g_vecs);

    __half* wqh = wh;
    __half* wkh = wh + (long)CC*CC;
    __half* wvh = wh + 2L*CC*CC;
    __half* wph = wh + 3L*CC*CC;

    const long SX = (long)CC * NN;
    const long SA = (long)NN * NN;
    const float isc = 1.0f / sqrtf((float)CC);
    const int WG = CC * CC / 4 / 256;   // conv grid for 512x512

    constexpr int SM_TF = SmemCfg<true,  false>::BYTES;
    constexpr int SM_FF = SmemCfg<false, false>::BYTES;
    constexpr int SM_FT = SmemCfg<false, true >::BYTES;
    cudaFuncSetAttribute(gemm_h<true,  false, 4, false>, cudaFuncAttributeMaxDynamicSharedMemorySize, SM_TF);
    cudaFuncSetAttribute(gemm_h<false, false, 4, false>, cudaFuncAttributeMaxDynamicSharedMemorySize, SM_FF);
    cudaFuncSetAttribute(gemm_h<false, false, 2, true >, cudaFuncAttributeMaxDynamicSharedMemorySize, SM_FF);
    cudaFuncSetAttribute(gemm_h<true,  false, 1, false>, cudaFuncAttributeMaxDynamicSharedMemorySize, SM_TF);
    cudaFuncSetAttribute(gemm_h<false, true,  0, true >, cudaFuncAttributeMaxDynamicSharedMemorySize, SM_FT);
    cudaFuncSetAttribute(gemm_h<false, false, 3, false>, cudaFuncAttributeMaxDynamicSharedMemorySize, SM_FF);

    // 0. zero split-K accumulators; convert weights to fp16
    zero_mm<<<256, 256>>>(m1f, m2f);
    conv_h<<<WG, 256>>>(wq, wqh);
    conv_h<<<WG, 256>>>(wk, wkh);
    conv_h<<<WG, 256>>>(wv, wvh);
    conv_h<<<WG, 256>>>(wp, wph);

    // 1. GroupNorm -> xnh (fp16)
    gn_kernel<<<BB * NG, 256>>>(x, gns, gnb, xnh);

    // 2. bias-derived vectors
    vecs_kernel<<<4, 512>>>(wq, wk, wp, bq, bk, bv, bp, vecs);

    // 3. M1 = Wq^T Wk, M2 = Wp Wv  (split-K=8), then convert to fp16
    gemm_h<true,  false, 4, false><<<dim3(4, 8, 8), 256, SM_TF>>>(
        wqh, 0, wkh, 0, m1f, 0, nullptr, 0, nullptr, 0, 64, CC, CC, CC, 1.0f);
    gemm_h<false, false, 4, false><<<dim3(4, 8, 8), 256, SM_FF>>>(
        wph, 0, wvh, 0, m2f, 0, nullptr, 0, nullptr, 0, 64, CC, CC, CC, 1.0f);
    conv_h<<<WG, 256>>>(m1f, m1h);
    conv_h<<<WG, 256>>>(m2f, m2h);

    // 4. t = M1 xn + tb[row]    (fp16 out)   M=512, N=1024, K=512
    gemm_h<false, false, 2, true><<<dim3(8, 8, BB), 256, SM_FF>>>(
        m1h, 0, xnh, SX, th, SX, vecs, 0, nullptr, 0, CC, CC, NN, NN, 1.0f);

    // 5. rvec
    rvec_kernel<<<dim3(NN/256, BB), 256>>>(xnh, vecs, rvec);

    // 6. S = (xn^T t + rvec[col]) / sqrt(C)  (fp32 out)  M=N=1024, K=512
    gemm_h<true, false, 1, false><<<dim3(8, 16, BB), 256, SM_TF>>>(
        xnh, SX, th, SX, S, SA, rvec, NN, nullptr, 0, CC, NN, NN, NN, isc);

    // 7. softmax -> fp16 probs
    softmax_kernel<<<BB * NN, 256>>>(S, Ph);

    // 8. z = xn P^T   (fp16 out)   M=512, N=1024, K=1024
    gemm_h<false, true, 0, true><<<dim3(8, 8, BB), 256, SM_FT>>>(
        xnh, SX, Ph, SA, zh, SX, nullptr, 0, nullptr, 0, NN, NN, NN, NN, 1.0f);

    // 9. out = M2 z + cb[row] + x   (fp32 out)   M=512, N=1024, K=512
    gemm_h<false, false, 3, false><<<dim3(8, 8, BB), 256, SM_FF>>>(
        m2h, 0, zh, SX, out, SX, vecs + 2*CC, 0, x, SX, CC, CC, NN, NN, 1.0f);
}

// round 17
// speedup vs baseline: 5.6675x; 1.0251x over previous
#include <cuda_runtime.h>
#include <cuda_fp16.h>
#include <mma.h>
#include <math.h>
#include <type_traits>

using namespace nvcuda;

// Problem constants
#define BB   16
#define CC   512
#define NN   1024
#define NG   32
#define CPG  16
#define GSZ  (CPG*NN)

#define TILE_M 128
#define TILE_N 128
#define TILE_K 64      // halves per K-chunk
#define HPAD   8       // pad halves (16B)

// Scratch (static device globals)
__device__ __half g_xnh[BB*CC*NN];   // group-normed x, fp16 [b][c][n]
__device__ __half g_th [BB*CC*NN];   // t = M1 xn + tb
__device__ float  g_S  [BB*NN*NN];   // logits (fp32)
__device__ __half g_Ph [BB*NN*NN];   // softmax probs (fp16)
__device__ __half g_zh [BB*CC*NN];   // z = xn A^T
__device__ float  g_M1f[CC*CC];      // split-K accumulators
__device__ float  g_M2f[CC*CC];
__device__ __half g_M1h[CC*CC];
__device__ __half g_M2h[CC*CC];
__device__ __half g_wh [4*CC*CC];    // fp16 weights: wq|wk|wv|wp
__device__ float  g_rvec[BB*NN];
__device__ float  g_vecs[3*CC + 32]; // tb | wt | cb | bqbk

// ---------------------------------------------------------------------------
__device__ __forceinline__ void cp_async16(void* smem, const void* gmem) {
    unsigned s = (unsigned)__cvta_generic_to_shared(smem);
    asm volatile("cp.async.cg.shared.global [%0], [%1], 16;\n" :: "r"(s), "l"(gmem));
}
__device__ __forceinline__ void cp_commit() {
    asm volatile("cp.async.commit_group;\n");
}
template<int N>
__device__ __forceinline__ void cp_wait() {
    asm volatile("cp.async.wait_group %0;\n" :: "n"(N));
}

// ---------------------------------------------------------------------------
// GroupNorm -> fp16 xn
// ---------------------------------------------------------------------------
__global__ __launch_bounds__(256) void gn_kernel(
    const float* __restrict__ x,
    const float* __restrict__ sc,
    const float* __restrict__ bi,
    __half* __restrict__ out)
{
    const int bg = blockIdx.x;
    const float* xp = x + (long)bg * GSZ;
    __half*      op = out + (long)bg * GSZ;

    float s = 0.f, s2 = 0.f;
    for (int i = threadIdx.x; i < GSZ / 4; i += 256) {
        float4 v = ((const float4*)xp)[i];
        s  += v.x + v.y + v.z + v.w;
        s2 += v.x*v.x + v.y*v.y + v.z*v.z + v.w*v.w;
    }
    #pragma unroll
    for (int o = 16; o > 0; o >>= 1) {
        s  += __shfl_xor_sync(~0u, s,  o);
        s2 += __shfl_xor_sync(~0u, s2, o);
    }
    __shared__ float rs[8], rs2[8];
    const int wid = threadIdx.x >> 5, lid = threadIdx.x & 31;
    if (lid == 0) { rs[wid] = s; rs2[wid] = s2; }
    __syncthreads();
    if (threadIdx.x == 0) {
        float ts = 0.f, ts2 = 0.f;
        #pragma unroll
        for (int w = 0; w < 8; w++) { ts += rs[w]; ts2 += rs2[w]; }
        rs[0] = ts; rs2[0] = ts2;
    }
    __syncthreads();
    const float inv_n = 1.0f / (float)GSZ;
    const float mean  = rs[0] * inv_n;
    const float var   = rs2[0] * inv_n - mean * mean;
    const float rstd  = rsqrtf(var + 1e-5f);

    const int g = bg % NG;
    for (int i = threadIdx.x; i < GSZ / 4; i += 256) {
        const int c = g * CPG + (i >> 8);
        const float a = rstd * sc[c];
        const float b = bi[c] - mean * a;
        float4 v = ((const float4*)xp)[i];
        ((__half2*)op)[2*i]   = __floats2half2_rn(v.x * a + b, v.y * a + b);
        ((__half2*)op)[2*i+1] = __floats2half2_rn(v.z * a + b, v.w * a + b);
    }
}

// ---------------------------------------------------------------------------
// Batched fp32 -> fp16 conversions (blockIdx.y selects tensor)
// ---------------------------------------------------------------------------
__global__ __launch_bounds__(256) void conv_w4(
    const float* __restrict__ s0, const float* __restrict__ s1,
    const float* __restrict__ s2, const float* __restrict__ s3,
    __half* __restrict__ d0)      // d = g_wh, laid out contiguously
{
    const float* srcs[4] = {s0, s1, s2, s3};
    const float* s = srcs[blockIdx.y];
    __half* d = d0 + (long)blockIdx.y * CC * CC;
    const int i = blockIdx.x * 256 + threadIdx.x;
    float4 v = ((const float4*)s)[i];
    ((__half2*)d)[2*i]   = __floats2half2_rn(v.x, v.y);
    ((__half2*)d)[2*i+1] = __floats2half2_rn(v.z, v.w);
}

__global__ __launch_bounds__(256) void conv_m2(
    const float* __restrict__ s0, const float* __restrict__ s1,
    __half* __restrict__ d0, __half* __restrict__ d1)
{
    const float* s = blockIdx.y ? s1 : s0;
    __half* d = blockIdx.y ? d1 : d0;
    const int i = blockIdx.x * 256 + threadIdx.x;
    float4 v = ((const float4*)s)[i];
    ((__half2*)d)[2*i]   = __floats2half2_rn(v.x, v.y);
    ((__half2*)d)[2*i+1] = __floats2half2_rn(v.z, v.w);
}

__global__ __launch_bounds__(256) void zero_mm(float* __restrict__ m1,
                                               float* __restrict__ m2)
{
    const int i = blockIdx.x * 256 + threadIdx.x;
    const float4 z = {0.f, 0.f, 0.f, 0.f};
    ((float4*)m1)[i] = z;
    ((float4*)m2)[i] = z;
}

// ---------------------------------------------------------------------------
// Bias-derived vectors
// ---------------------------------------------------------------------------
__global__ __launch_bounds__(512) void vecs_kernel(
    const float* __restrict__ wq, const float* __restrict__ wk,
    const float* __restrict__ wp,
    const float* __restrict__ bq, const float* __restrict__ bk,
    const float* __restrict__ bv, const float* __restrict__ bp,
    float* __restrict__ vecs)
{
    const int t = threadIdx.x;
    if (blockIdx.x == 0) {
        float s = 0.f;
        for (int d = 0; d < CC; d++) s += wq[d*CC + t] * bk[d];
        vecs[t] = s;
    } else if (blockIdx.x == 1) {
        float s = 0.f;
        for (int d = 0; d < CC; d++) s += wk[d*CC + t] * bq[d];
        vecs[CC + t] = s;
    } else if (blockIdx.x == 2) {
        float s = 0.f;
        for (int d = 0; d < CC; d++) s += wp[t*CC + d] * bv[d];
        vecs[2*CC + t] = s + bp[t];
    } else {
        __shared__ float red[16];
        float s = bq[t] * bk[t];
        #pragma unroll
        for (int o = 16; o > 0; o >>= 1) s += __shfl_xor_sync(~0u, s, o);
        if ((t & 31) == 0) red[t >> 5] = s;
        __syncthreads();
        if (t == 0) {
            float ts = 0.f;
            #pragma unroll
            for (int w = 0; w < 16; w++) ts += red[w];
            vecs[3*CC] = ts;
        }
    }
}

// ---------------------------------------------------------------------------
// rvec[b][j] = wt . xn[b][:,j] + bqbk
// ---------------------------------------------------------------------------
__global__ __launch_bounds__(256) void rvec_kernel(
    const __half* __restrict__ xn, const float* __restrict__ vecs,
    float* __restrict__ rvec)
{
    __shared__ float wt[CC];
    const int b = blockIdx.y;
    const int j = blockIdx.x * 256 + threadIdx.x;
    for (int i = threadIdx.x; i < CC; i += 256) wt[i] = vecs[CC + i];
    __syncthreads();
    const __half* xb = xn + (long)b * CC * NN + j;
    float s = 0.f;
    #pragma unroll 8
    for (int c = 0; c < CC; c++) s += wt[c] * __half2float(xb[(long)c * NN]);
    rvec[b * NN + j] = s + vecs[3*CC];
}

// ---------------------------------------------------------------------------
// FP16 tensor-core GEMM (fp32 accumulate). 128x128 block tile, 8 warps of
// 64x32 (m16n16k16 4x2), TILE_K=64, 2-stage cp.async, 2 CTAs/SM.
//   TA: A(m,k) = A[k*lda + m]   TB: B(k,n) = B[n*ldb + k]
// EPI: 0: C = alpha*acc                   (OUTH)
//      1: C = alpha*(acc + bias[b][n])    (fp32 out)
//      2: C = acc + bias[m]               (OUTH)
//      3: C = acc + bias[m] + resid       (fp32 out)
//      4: atomicAdd(fp32 C); z = K-slice
// ---------------------------------------------------------------------------
template<bool TA, bool TB>
struct SmemCfg {
    static constexpr int A_LD   = TA ? (TILE_M + HPAD) : (TILE_K + HPAD);
    static constexpr int A_SIZE = TA ? TILE_K * A_LD   : TILE_M * A_LD;
    static constexpr int B_LD   = TB ? (TILE_K + HPAD) : (TILE_N + HPAD);
    static constexpr int B_SIZE = TB ? TILE_N * B_LD   : TILE_K * B_LD;
    static constexpr int PIPE   = (2 * A_SIZE + 2 * B_SIZE) * 2;
    static constexpr int EPIB   = TILE_M * TILE_N * 4;
    static constexpr int BYTES  = PIPE > EPIB ? PIPE : EPIB;
};

template<bool TA, bool TB, int EPI, bool OUTH>
__global__ __launch_bounds__(256, 2) void gemm_h(
    const __half* __restrict__ Ag, long sA,
    const __half* __restrict__ Bg, long sB,
    void*         __restrict__ Cg, long sC,
    const float* __restrict__ bias, long sBias,
    const float* __restrict__ resid, long sR,
    int K, int lda, int ldb, int ldc, float alpha)
{
    using Cfg = SmemCfg<TA, TB>;
    constexpr int A_LD = Cfg::A_LD, A_SIZE = Cfg::A_SIZE;
    constexpr int B_LD = Cfg::B_LD, B_SIZE = Cfg::B_SIZE;

    extern __shared__ __half smem[];
    __half* AsBase = smem;
    __half* BsBase = smem + 2 * A_SIZE;

    const int zz = blockIdx.z;
    const int b  = (EPI == 4) ? 0 : zz;
    const int koff = (EPI == 4) ? zz * K : 0;
    const __half* A = Ag + b * sA;
    const __half* B = Bg + b * sB;

    const int m0 = blockIdx.y * TILE_M;
    const int n0 = blockIdx.x * TILE_N;
    const int tid = threadIdx.x;
    const int wid = tid >> 5;
    const int wm = wid >> 2;    // 2 warp rows (64 m each)
    const int wn = wid & 3;     // 4 warp cols (32 n each)

    typedef typename std::conditional<TA, wmma::col_major, wmma::row_major>::type ALay;
    typedef typename std::conditional<TB, wmma::col_major, wmma::row_major>::type BLay;

    wmma::fragment<wmma::accumulator, 16, 16, 16, float> acc[4][2];
    #pragma unroll
    for (int i = 0; i < 4; i++)
        #pragma unroll
        for (int j = 0; j < 2; j++)
            wmma::fill_fragment(acc[i][j], 0.0f);

    auto load_tiles = [&](int s, int k0) {
        __half* as = AsBase + s * A_SIZE;
        __half* bs = BsBase + s * B_SIZE;
        const int kg = koff + k0;
        // A tile: 128x64 halves = 1024 16B-chunks (4/thread)
        if (!TA) {
            #pragma unroll
            for (int p = 0; p < 4; p++) {
                const int c = tid + p * 256;
                const int m = c >> 3, kc = c & 7;
                cp_async16(&as[m * A_LD + kc * 8],
                           A + (long)(m0 + m) * lda + kg + kc * 8);
            }
        } else {
            #pragma unroll
            for (int p = 0; p < 4; p++) {
                const int c = tid + p * 256;
                const int kk = c >> 4, mc = c & 15;
                cp_async16(&as[kk * A_LD + mc * 8],
                           A + (long)(kg + kk) * lda + m0 + mc * 8);
            }
        }
        // B tile: 64x128 halves = 1024 chunks (4/thread)
        if (!TB) {
            #pragma unroll
            for (int p = 0; p < 4; p++) {
                const int c = tid + p * 256;
                const int kk = c >> 4, nc = c & 15;
                cp_async16(&bs[kk * B_LD + nc * 8],
                           B + (long)(kg + kk) * ldb + n0 + nc * 8);
            }
        } else {
            #pragma unroll
            for (int p = 0; p < 4; p++) {
                const int c = tid + p * 256;
                const int n = c >> 3, kc = c & 7;
                cp_async16(&bs[n * B_LD + kc * 8],
                           B + (long)(n0 + n) * ldb + kg + kc * 8);
            }
        }
    };

    const int KT = K / TILE_K;
    load_tiles(0, 0);
    cp_commit();

    for (int kt = 0; kt < KT; kt++) {
        const int s = kt & 1;
        cp_wait<0>();
        __syncthreads();

        if (kt + 1 < KT) {
            load_tiles(s ^ 1, (kt + 1) * TILE_K);
            cp_commit();
        }

        const __half* as = AsBase + s * A_SIZE;
        const __half* bs = BsBase + s * B_SIZE;
        #pragma unroll
        for (int kf = 0; kf < TILE_K / 16; kf++) {
            wmma::fragment<wmma::matrix_a, 16, 16, 16, __half, ALay> af[4];
            wmma::fragment<wmma::matrix_b, 16, 16, 16, __half, BLay> bf[2];
            #pragma unroll
            for (int i = 0; i < 4; i++) {
                const __half* p = TA ? &as[(kf*16) * A_LD + wm*64 + i*16]
                                     : &as[(wm*64 + i*16) * A_LD + kf*16];
                wmma::load_matrix_sync(af[i], p, A_LD);
            }
            #pragma unroll
            for (int j = 0; j < 2; j++) {
                const __half* p = TB ? &bs[(wn*32 + j*16) * B_LD + kf*16]
                                     : &bs[(kf*16) * B_LD + wn*32 + j*16];
                wmma::load_matrix_sync(bf[j], p, B_LD);
            }
            #pragma unroll
            for (int i = 0; i < 4; i++)
                #pragma unroll
                for (int j = 0; j < 2; j++)
                    wmma::mma_sync(acc[i][j], af[i], bf[j], acc[i][j]);
        }
    }

    // ---- epilogue: stage tile in smem (fp32), then elementwise ----
    __syncthreads();
    float* cs = (float*)smem;
    #pragma unroll
    for (int i = 0; i < 4; i++)
        #pragma unroll
        for (int j = 0; j < 2; j++)
            wmma::store_matrix_sync(&cs[(wm*64 + i*16) * TILE_N + wn*32 + j*16],
                                    acc[i][j], TILE_N, wmma::mem_row_major);
    __syncthreads();

    if (EPI == 4) {
        float* C = (float*)Cg;
        for (int idx = tid; idx < TILE_M * TILE_N; idx += 256) {
            const int m = idx >> 7, n = idx & 127;
            atomicAdd(&C[(long)(m0 + m) * ldc + n0 + n], cs[idx]);
        }
    } else {
        const float* bb = (EPI == 1) ? bias + zz * sBias : bias;
        #pragma unroll
        for (int p = 0; p < TILE_M * TILE_N / 4 / 256; p++) {
            const int idx = tid + p * 256;
            const int m = idx >> 5, nc = (idx & 31) * 4;
            float4 v = *(float4*)&cs[m * TILE_N + nc];
            if (EPI == 0) {
                v.x *= alpha; v.y *= alpha; v.z *= alpha; v.w *= alpha;
            } else if (EPI == 1) {
                const int n = n0 + nc;
                v.x = (v.x + bb[n+0]) * alpha;
                v.y = (v.y + bb[n+1]) * alpha;
                v.z = (v.z + bb[n+2]) * alpha;
                v.w = (v.w + bb[n+3]) * alpha;
            } else {
                const float rb = bias[m0 + m];
                v.x += rb; v.y += rb; v.z += rb; v.w += rb;
                if (EPI == 3) {
                    float4 r = *(const float4*)&resid[zz * sR + (long)(m0+m) * ldc + n0 + nc];
                    v.x += r.x; v.y += r.y; v.z += r.z; v.w += r.w;
                }
            }
            const long base = (long)b * sC + (long)(m0 + m) * ldc + n0 + nc;
            if (OUTH) {
                __half2* Ch = (__half2*)((__half*)Cg + base);
                Ch[0] = __floats2half2_rn(v.x, v.y);
                Ch[1] = __floats2half2_rn(v.z, v.w);
            } else {
                *(float4*)((float*)Cg + base) = v;
            }
        }
    }
}

// ---------------------------------------------------------------------------
// Row softmax: fp32 logits in, fp16 probs out
// ---------------------------------------------------------------------------
__global__ __launch_bounds__(256) void softmax_kernel(
    const float* __restrict__ S, __half* __restrict__ P)
{
    const float* row = S + (long)blockIdx.x * NN;
    __half*      po  = P + (long)blockIdx.x * NN;
    const int tid = threadIdx.x;
    const int wid = tid >> 5, lid = tid & 31;
    __shared__ float sred[8];

    float4 v = ((const float4*)row)[tid];
    float mx = fmaxf(fmaxf(v.x, v.y), fmaxf(v.z, v.w));
    #pragma unroll
    for (int o = 16; o > 0; o >>= 1) mx = fmaxf(mx, __shfl_xor_sync(~0u, mx, o));
    if (lid == 0) sred[wid] = mx;
    __syncthreads();
    if (wid == 0) {
        float m2 = (lid < 8) ? sred[lid] : -1e30f;
        #pragma unroll
        for (int o = 4; o > 0; o >>= 1) m2 = fmaxf(m2, __shfl_xor_sync(~0u, m2, o));
        if (lid == 0) sred[0] = m2;
    }
    __syncthreads();
    mx = sred[0];

    v.x = __expf(v.x - mx); v.y = __expf(v.y - mx);
    v.z = __expf(v.z - mx); v.w = __expf(v.w - mx);
    float s = v.x + v.y + v.z + v.w;
    #pragma unroll
    for (int o = 16; o > 0; o >>= 1) s += __shfl_xor_sync(~0u, s, o);
    __syncthreads();
    if (lid == 0) sred[wid] = s;
    __syncthreads();
    if (wid == 0) {
        float t = (lid < 8) ? sred[lid] : 0.f;
        #pragma unroll
        for (int o = 4; o > 0; o >>= 1) t += __shfl_xor_sync(~0u, t, o);
        if (lid == 0) sred[0] = t;
    }
    __syncthreads();
    const float inv = 1.0f / sred[0];
    ((__half2*)po)[2*tid]   = __floats2half2_rn(v.x * inv, v.y * inv);
    ((__half2*)po)[2*tid+1] = __floats2half2_rn(v.z * inv, v.w * inv);
}

// ---------------------------------------------------------------------------
extern "C" void kernel_launch(void* const* d_in, const int* in_sizes, int n_in,
                              void* d_out, int out_size)
{
    const float* x   = (const float*)d_in[0];
    const float* gns = (const float*)d_in[1];
    const float* gnb = (const float*)d_in[2];
    const float* wq  = (const float*)d_in[3];
    const float* bq  = (const float*)d_in[4];
    const float* wk  = (const float*)d_in[5];
    const float* bk  = (const float*)d_in[6];
    const float* wv  = (const float*)d_in[7];
    const float* bv  = (const float*)d_in[8];
    const float* wp  = (const float*)d_in[9];
    const float* bp  = (const float*)d_in[10];
    float* out = (float*)d_out;

    __half *xnh, *th, *Ph, *zh, *m1h, *m2h, *wh;
    float *S, *m1f, *m2f, *rvec, *vecs;
    cudaGetSymbolAddress((void**)&xnh,  g_xnh);
    cudaGetSymbolAddress((void**)&th,   g_th);
    cudaGetSymbolAddress((void**)&S,    g_S);
    cudaGetSymbolAddress((void**)&Ph,   g_Ph);
    cudaGetSymbolAddress((void**)&zh,   g_zh);
    cudaGetSymbolAddress((void**)&m1f,  g_M1f);
    cudaGetSymbolAddress((void**)&m2f,  g_M2f);
    cudaGetSymbolAddress((void**)&m1h,  g_M1h);
    cudaGetSymbolAddress((void**)&m2h,  g_M2h);
    cudaGetSymbolAddress((void**)&wh,   g_wh);
    cudaGetSymbolAddress((void**)&rvec, g_rvec);
    cudaGetSymbolAddress((void**)&vecs, g_vecs);

    __half* wqh = wh;
    __half* wkh = wh + (long)CC*CC;
    __half* wvh = wh + 2L*CC*CC;
    __half* wph = wh + 3L*CC*CC;

    const long SX = (long)CC * NN;
    const long SA = (long)NN * NN;
    const float isc = 1.0f / sqrtf((float)CC);
    const int WG = CC * CC / 4 / 256;

    constexpr int SM_TF = SmemCfg<true,  false>::BYTES;
    constexpr int SM_FF = SmemCfg<false, false>::BYTES;
    constexpr int SM_FT = SmemCfg<false, true >::BYTES;
    cudaFuncSetAttribute(gemm_h<true,  false, 4, false>, cudaFuncAttributeMaxDynamicSharedMemorySize, SM_TF);
    cudaFuncSetAttribute(gemm_h<false, false, 4, false>, cudaFuncAttributeMaxDynamicSharedMemorySize, SM_FF);
    cudaFuncSetAttribute(gemm_h<false, false, 2, true >, cudaFuncAttributeMaxDynamicSharedMemorySize, SM_FF);
    cudaFuncSetAttribute(gemm_h<true,  false, 1, false>, cudaFuncAttributeMaxDynamicSharedMemorySize, SM_TF);
    cudaFuncSetAttribute(gemm_h<false, true,  0, true >, cudaFuncAttributeMaxDynamicSharedMemorySize, SM_FT);
    cudaFuncSetAttribute(gemm_h<false, false, 3, false>, cudaFuncAttributeMaxDynamicSharedMemorySize, SM_FF);

    // 0. zero split-K accumulators; convert 4 weights in ONE launch
    zero_mm<<<256, 256>>>(m1f, m2f);
    conv_w4<<<dim3(WG, 4), 256>>>(wq, wk, wv, wp, wh);

    // 1. GroupNorm -> xnh
    gn_kernel<<<BB * NG, 256>>>(x, gns, gnb, xnh);

    // 2. bias-derived vectors
    vecs_kernel<<<4, 512>>>(wq, wk, wp, bq, bk, bv, bp, vecs);

    // 3. M1 = Wq^T Wk, M2 = Wp Wv  (split-K=8), convert both in ONE launch
    gemm_h<true,  false, 4, false><<<dim3(4, 4, 8), 256, SM_TF>>>(
        wqh, 0, wkh, 0, m1f, 0, nullptr, 0, nullptr, 0, 64, CC, CC, CC, 1.0f);
    gemm_h<false, false, 4, false><<<dim3(4, 4, 8), 256, SM_FF>>>(
        wph, 0, wvh, 0, m2f, 0, nullptr, 0, nullptr, 0, 64, CC, CC, CC, 1.0f);
    conv_m2<<<dim3(WG, 2), 256>>>(m1f, m2f, m1h, m2h);

    // 4. t = M1 xn + tb[row]    (fp16 out)   M=512, N=1024, K=512
    gemm_h<false, false, 2, true><<<dim3(8, 4, BB), 256, SM_FF>>>(
        m1h, 0, xnh, SX, th, SX, vecs, 0, nullptr, 0, CC, CC, NN, NN, 1.0f);

    // 5. rvec
    rvec_kernel<<<dim3(NN/256, BB), 256>>>(xnh, vecs, rvec);

    // 6. S = (xn^T t + rvec[col]) / sqrt(C)  (fp32 out)  M=N=1024, K=512
    gemm_h<true, false, 1, false><<<dim3(8, 8, BB), 256, SM_TF>>>(
        xnh, SX, th, SX, S, SA, rvec, NN, nullptr, 0, CC, NN, NN, NN, isc);

    // 7. softmax -> fp16 probs
    softmax_kernel<<<BB * NN, 256>>>(S, Ph);

    // 8. z = xn P^T   (fp16 out)   M=512, N=1024, K=1024
    gemm_h<false, true, 0, true><<<dim3(8, 4, BB), 256, SM_FT>>>(
        xnh, SX, Ph, SA, zh, SX, nullptr, 0, nullptr, 0, NN, NN, NN, NN, 1.0f);

    // 9. out = M2 z + cb[row] + x   (fp32 out)   M=512, N=1024, K=512
    gemm_h<false, false, 3, false><<<dim3(8, 4, BB), 256, SM_FF>>>(
        m2h, 0, zh, SX, out, SX, vecs + 2*CC, 0, x, SX, CC, CC, NN, NN, 1.0f);
}